// round 5
// baseline (speedup 1.0000x reference)
#include <cuda_runtime.h>
#include <math.h>
#include <stdint.h>

#define NB 2
#define NL 2048
#define NS 2048
#define NH 8
#define NE 64
#define NBH 16
#define SCALE 0.125f
#define TQ 128
#define TN 64
#define NQT (NL / TQ)
#define NKT (NS / TN)

// ---------------- device scratch ----------------
__device__ __align__(16) uint8_t g_kf[NBH][NKT][2][8192];
__device__ __align__(16) uint8_t g_vf[NBH][NKT][2][8192];
__device__ unsigned char g_mk[NB * NS];
__device__ unsigned char g_mq[NB * NL];

// ---------------- helpers ----------------
__device__ __forceinline__ uint32_t bf16_bits(float x) {
    uint32_t fb = __float_as_uint(x);
    return (fb + 0x7fffu + ((fb >> 16) & 1u)) >> 16;
}
__device__ __forceinline__ float bf16_f(float x) {
    return __uint_as_float(bf16_bits(x) << 16);
}
__device__ __forceinline__ uint32_t packbf(float lo_elem, float hi_elem) {
    return bf16_bits(lo_elem) | (bf16_bits(hi_elem) << 16);
}
__device__ __forceinline__ uint32_t smem_u32(const void* p) {
    uint32_t a;
    asm("{ .reg .u64 t; cvta.to.shared.u64 t, %1; cvt.u32.u64 %0, t; }" : "=r"(a) : "l"(p));
    return a;
}
__device__ __forceinline__ void mma16816(float d[4], const uint32_t a[4],
                                         uint32_t b0, uint32_t b1) {
    asm volatile(
        "mma.sync.aligned.m16n8k16.row.col.f32.bf16.bf16.f32 "
        "{%0,%1,%2,%3},{%4,%5,%6,%7},{%8,%9},{%0,%1,%2,%3};"
        : "+f"(d[0]), "+f"(d[1]), "+f"(d[2]), "+f"(d[3])
        : "r"(a[0]), "r"(a[1]), "r"(a[2]), "r"(a[3]), "r"(b0), "r"(b1));
}
__device__ __forceinline__ void cpa16(uint32_t dst, const void* src) {
    asm volatile("cp.async.cg.shared.global [%0], [%1], 16;" :: "r"(dst), "l"(src));
}
#define CPA_COMMIT() asm volatile("cp.async.commit_group;" ::: "memory")
#define CPA_WAIT0()  asm volatile("cp.async.wait_group 0;" ::: "memory")
#define CPA_WAIT1()  asm volatile("cp.async.wait_group 1;" ::: "memory")

// ---------------- mask prep (dtype-agnostic) ----------------
__global__ void mask_prep_kernel(const void* mk_raw, const void* mq_raw) {
    __shared__ int sh_f32, sh_u8;
    if (threadIdx.x == 0) { sh_f32 = 0; sh_u8 = 0; }
    __syncthreads();
    const unsigned char* p = (const unsigned char*)mk_raw;
    int f32 = 0, u8 = 0;
    for (int idx = threadIdx.x; idx < NB * NS; idx += blockDim.x) {
        unsigned char vv = p[idx];
        int m = idx & 3;
        if (m == 3 && vv == 0x3f) f32 = 1;
        else if (m != 0 && vv != 0) u8 = 1;
    }
    if (f32) atomicOr(&sh_f32, 1);
    if (u8) atomicOr(&sh_u8, 1);
    __syncthreads();
    int mode = sh_f32 ? 2 : (sh_u8 ? 1 : 0);
    for (int idx = threadIdx.x; idx < NB * NS; idx += blockDim.x) {
        unsigned char vk, vq;
        if (mode == 2) { vk = ((const float*)mk_raw)[idx] != 0.0f; vq = ((const float*)mq_raw)[idx] != 0.0f; }
        else if (mode == 1) { vk = ((const unsigned char*)mk_raw)[idx] != 0; vq = ((const unsigned char*)mq_raw)[idx] != 0; }
        else { vk = ((const int*)mk_raw)[idx] != 0; vq = ((const int*)mq_raw)[idx] != 0; }
        g_mk[idx] = vk;
        g_mq[idx] = vq;
    }
}

// ---------------- prep: fragment-ordered bf16 hi/lo split ----------------
__global__ __launch_bounds__(256) void prep_kernel(const float* __restrict__ k,
                                                   const float* __restrict__ v) {
    const int kind = blockIdx.x >> 10;                   // 0 = K, 1 = V^T
    const int c = ((blockIdx.x & 1023) << 8) + threadIdx.x;
    const int lane = c & 31;
    const int chunk = (c >> 5) & 1;
    const int bn = (c >> 6) & 7;
    const int kt = (c >> 9) & 31;
    const int bh = c >> 14;
    const int b = bh >> 3, h = bh & 7;
    const int c2 = lane & 3, trow = lane >> 2;

    uint32_t hi[4], lo[4];
    if (kind == 0) {
        const int j = kt * 64 + bn * 8 + trow;
        const float* base = k + ((size_t)(b * NS + j) * NH + h) * NE;
        #pragma unroll
        for (int kc_in = 0; kc_in < 2; kc_in++) {
            #pragma unroll
            for (int kh = 0; kh < 2; kh++) {
                int e = (chunk * 2 + kc_in) * 16 + kh * 8 + 2 * c2;
                float2 x = *(const float2*)(base + e);
                int idx = kc_in * 2 + kh;
                hi[idx] = packbf(x.x, x.y);
                lo[idx] = packbf(x.x - bf16_f(x.x), x.y - bf16_f(x.y));
            }
        }
        uint32_t off = bn * 1024 + chunk * 512 + lane * 16;
        *(uint4*)(&g_kf[bh][kt][0][off]) = make_uint4(hi[0], hi[1], hi[2], hi[3]);
        *(uint4*)(&g_kf[bh][kt][1][off]) = make_uint4(lo[0], lo[1], lo[2], lo[3]);
    } else {
        const int e = bn * 8 + trow;
        #pragma unroll
        for (int kc_in = 0; kc_in < 2; kc_in++) {
            #pragma unroll
            for (int kh = 0; kh < 2; kh++) {
                int jb = kt * 64 + (chunk * 2 + kc_in) * 16 + kh * 8 + 2 * c2;
                float x0 = v[((size_t)(b * NS + jb) * NH + h) * NE + e];
                float x1 = v[((size_t)(b * NS + jb + 1) * NH + h) * NE + e];
                int idx = kc_in * 2 + kh;
                hi[idx] = packbf(x0, x1);
                lo[idx] = packbf(x0 - bf16_f(x0), x1 - bf16_f(x1));
            }
        }
        uint32_t off = bn * 1024 + chunk * 512 + lane * 16;
        *(uint4*)(&g_vf[bh][kt][0][off]) = make_uint4(hi[0], hi[1], hi[2], hi[3]);
        *(uint4*)(&g_vf[bh][kt][1][off]) = make_uint4(lo[0], lo[1], lo[2], lo[3]);
    }
}

// ---------------- attention: mma.sync bf16 3-pass flash + fused normalize ----------------
#define SM_BYTES (65536 + 256)

__global__ __launch_bounds__(256, 1) void attn_mma_kernel(const float* __restrict__ q,
                                                          float* __restrict__ outV,
                                                          float* __restrict__ outA,
                                                          float* __restrict__ outE) {
    extern __shared__ __align__(16) char sm[];
    const int tid = threadIdx.x;
    const int w = tid >> 5;
    const int lane = tid & 31;
    const int c2 = lane & 3, trow = lane >> 2;

    const int qt = (NQT - 1) - (blockIdx.x >> 4);
    const int bh = blockIdx.x & 15;
    const int b = bh >> 3, h = bh & 7;
    const int i0 = qt * TQ;
    const int nk = 2 * qt + 2;

    const int i_r0 = i0 + w * 16 + trow;
    const int i_r1 = i_r0 + 8;
    const int i_wmax = i0 + w * 16 + 15;

    const uint32_t smb = smem_u32(sm);

    // Q fragments (hi/lo), register-resident
    uint32_t qh[4][4], ql[4][4];
    {
        const float* q0 = q + ((size_t)(b * NL + i_r0) * NH + h) * NE;
        const float* q1 = q + ((size_t)(b * NL + i_r1) * NH + h) * NE;
        #pragma unroll
        for (int kc = 0; kc < 4; kc++) {
            int e = kc * 16 + 2 * c2;
            float2 a0 = *(const float2*)(q0 + e);
            float2 a1 = *(const float2*)(q1 + e);
            float2 b0 = *(const float2*)(q0 + e + 8);
            float2 b1 = *(const float2*)(q1 + e + 8);
            qh[kc][0] = packbf(a0.x, a0.y); qh[kc][1] = packbf(a1.x, a1.y);
            qh[kc][2] = packbf(b0.x, b0.y); qh[kc][3] = packbf(b1.x, b1.y);
            ql[kc][0] = packbf(a0.x - bf16_f(a0.x), a0.y - bf16_f(a0.y));
            ql[kc][1] = packbf(a1.x - bf16_f(a1.x), a1.y - bf16_f(a1.y));
            ql[kc][2] = packbf(b0.x - bf16_f(b0.x), b0.y - bf16_f(b0.y));
            ql[kc][3] = packbf(b1.x - bf16_f(b1.x), b1.y - bf16_f(b1.y));
        }
    }

    float sacc[8][4];
    float oacc[8][4];
    #pragma unroll
    for (int bn = 0; bn < 8; bn++)
        #pragma unroll
        for (int u = 0; u < 4; u++) { sacc[bn][u] = 0.0f; oacc[bn][u] = 0.0f; }

    float lsum0 = 0.0f, lsum1 = 0.0f, esum0 = 0.0f, esum1 = 0.0f;
    float* Arow0 = outA + ((size_t)bh * NL + i_r0) * NS;
    float* Arow1 = outA + ((size_t)bh * NL + i_r1) * NS;

    auto stage = [&](int bufid, int kt) {
        const char* srcK = (const char*)g_kf[bh][kt];
        const char* srcV = (const char*)g_vf[bh][kt];
        uint32_t dst = smb + bufid * 32768;
        #pragma unroll
        for (int i = 0; i < 4; i++) {
            uint32_t off = (uint32_t)(i * 256 + tid) * 16;
            cpa16(dst + off, srcK + off);
            cpa16(dst + 16384 + off, srcV + off);
        }
        if (tid < 16)
            *(uint32_t*)(sm + 65536 + bufid * 64 + tid * 4) =
                *(const uint32_t*)(g_mk + b * NS + kt * 64 + tid * 4);
    };

    stage(0, 0);
    CPA_COMMIT();

    const float4 z4 = make_float4(0, 0, 0, 0);

    int buf = 0;
    for (int kt = 0; kt < nk; kt++) {
        if (kt + 1 < nk) { stage(buf ^ 1, kt + 1); CPA_COMMIT(); CPA_WAIT1(); }
        else CPA_WAIT0();
        __syncthreads();

        const int j0 = kt * TN;
        if (j0 <= i_wmax) {
            const char* bufp = sm + buf * 32768;
            const unsigned char* msk = (const unsigned char*)(sm + 65536 + buf * 64);

            // ---- QK: 3-pass bf16 ----
            #pragma unroll
            for (int bn = 0; bn < 8; bn++) {
                uint4 h0 = *(const uint4*)(bufp + bn * 1024 + lane * 16);
                uint4 h1 = *(const uint4*)(bufp + bn * 1024 + 512 + lane * 16);
                uint4 l0 = *(const uint4*)(bufp + 8192 + bn * 1024 + lane * 16);
                uint4 l1 = *(const uint4*)(bufp + 8192 + bn * 1024 + 512 + lane * 16);
                mma16816(sacc[bn], qh[0], h0.x, h0.y);
                mma16816(sacc[bn], qh[1], h0.z, h0.w);
                mma16816(sacc[bn], qh[2], h1.x, h1.y);
                mma16816(sacc[bn], qh[3], h1.z, h1.w);
                mma16816(sacc[bn], qh[0], l0.x, l0.y);
                mma16816(sacc[bn], qh[1], l0.z, l0.w);
                mma16816(sacc[bn], qh[2], l1.x, l1.y);
                mma16816(sacc[bn], qh[3], l1.z, l1.w);
                mma16816(sacc[bn], ql[0], h0.x, h0.y);
                mma16816(sacc[bn], ql[1], h0.z, h0.w);
                mma16816(sacc[bn], ql[2], h1.x, h1.y);
                mma16816(sacc[bn], ql[3], h1.z, h1.w);
            }

            // ---- epilogue: exp, sums, unnormalized A store, P frags ----
            uint32_t pa_hi[4][4], pa_lo[4][4];
            #pragma unroll
            for (int bn = 0; bn < 8; bn++) {
                int colb = j0 + bn * 8 + 2 * c2;
                float s00 = sacc[bn][0] * SCALE, s01 = sacc[bn][1] * SCALE;
                float s10 = sacc[bn][2] * SCALE, s11 = sacc[bn][3] * SCALE;
                unsigned char m0 = msk[bn * 8 + 2 * c2];
                unsigned char m1 = msk[bn * 8 + 2 * c2 + 1];
                float e00 = (m0 || colb > i_r0) ? 0.0f : __expf(s00);
                float e01 = (m1 || colb + 1 > i_r0) ? 0.0f : __expf(s01);
                float e10 = (m0 || colb > i_r1) ? 0.0f : __expf(s10);
                float e11 = (m1 || colb + 1 > i_r1) ? 0.0f : __expf(s11);
                lsum0 += e00 + e01; esum0 += e00 * s00 + e01 * s01;
                lsum1 += e10 + e11; esum1 += e10 * s10 + e11 * s11;
                *(float2*)(Arow0 + colb) = make_float2(e00, e01);
                *(float2*)(Arow1 + colb) = make_float2(e10, e11);
                int kc = bn >> 1, s0i = (bn & 1) * 2;
                pa_hi[kc][s0i + 0] = packbf(e00, e01);
                pa_hi[kc][s0i + 1] = packbf(e10, e11);
                pa_lo[kc][s0i + 0] = packbf(e00 - bf16_f(e00), e01 - bf16_f(e01));
                pa_lo[kc][s0i + 1] = packbf(e10 - bf16_f(e10), e11 - bf16_f(e11));
                sacc[bn][0] = 0.0f; sacc[bn][1] = 0.0f;
                sacc[bn][2] = 0.0f; sacc[bn][3] = 0.0f;
            }

            // ---- AV: 3-pass bf16 ----
            #pragma unroll
            for (int bn = 0; bn < 8; bn++) {
                uint4 h0 = *(const uint4*)(bufp + 16384 + bn * 1024 + lane * 16);
                uint4 h1 = *(const uint4*)(bufp + 16384 + bn * 1024 + 512 + lane * 16);
                uint4 l0 = *(const uint4*)(bufp + 24576 + bn * 1024 + lane * 16);
                uint4 l1 = *(const uint4*)(bufp + 24576 + bn * 1024 + 512 + lane * 16);
                mma16816(oacc[bn], pa_hi[0], h0.x, h0.y);
                mma16816(oacc[bn], pa_hi[1], h0.z, h0.w);
                mma16816(oacc[bn], pa_hi[2], h1.x, h1.y);
                mma16816(oacc[bn], pa_hi[3], h1.z, h1.w);
                mma16816(oacc[bn], pa_hi[0], l0.x, l0.y);
                mma16816(oacc[bn], pa_hi[1], l0.z, l0.w);
                mma16816(oacc[bn], pa_hi[2], l1.x, l1.y);
                mma16816(oacc[bn], pa_hi[3], l1.z, l1.w);
                mma16816(oacc[bn], pa_lo[0], h0.x, h0.y);
                mma16816(oacc[bn], pa_lo[1], h0.z, h0.w);
                mma16816(oacc[bn], pa_lo[2], h1.x, h1.y);
                mma16816(oacc[bn], pa_lo[3], h1.z, h1.w);
            }
        } else {
            // above-diagonal tile for this warp: write zeros (16 rows x 64 cols)
            #pragma unroll
            for (int rr = 0; rr < 2; rr++) {
                float* Ar = (rr == 0 ? Arow0 : Arow1) + j0;
                #pragma unroll
                for (int u = 0; u < 4; u++)
                    ((float4*)Ar)[c2 * 4 + u] = z4;
            }
        }
        buf ^= 1;
        __syncthreads();
    }

    // ---- stats: quad reduce, O write, entropy ----
    lsum0 += __shfl_xor_sync(0xffffffffu, lsum0, 1);
    lsum0 += __shfl_xor_sync(0xffffffffu, lsum0, 2);
    lsum1 += __shfl_xor_sync(0xffffffffu, lsum1, 1);
    lsum1 += __shfl_xor_sync(0xffffffffu, lsum1, 2);
    esum0 += __shfl_xor_sync(0xffffffffu, esum0, 1);
    esum0 += __shfl_xor_sync(0xffffffffu, esum0, 2);
    esum1 += __shfl_xor_sync(0xffffffffu, esum1, 1);
    esum1 += __shfl_xor_sync(0xffffffffu, esum1, 2);

    const bool mq0 = g_mq[b * NL + i_r0] != 0;
    const bool mq1 = g_mq[b * NL + i_r1] != 0;
    const float inv0 = mq0 ? 0.0f : 1.0f / lsum0;
    const float inv1 = mq1 ? 0.0f : 1.0f / lsum1;

    float* vo0 = outV + ((size_t)(b * NL + i_r0) * NH + h) * NE;
    float* vo1 = outV + ((size_t)(b * NL + i_r1) * NH + h) * NE;
    #pragma unroll
    for (int bn = 0; bn < 8; bn++) {
        int e0 = bn * 8 + 2 * c2;
        *(float2*)(vo0 + e0) = make_float2(oacc[bn][0] * inv0, oacc[bn][1] * inv0);
        *(float2*)(vo1 + e0) = make_float2(oacc[bn][2] * inv1, oacc[bn][3] * inv1);
    }
    if (c2 == 0) {
        outE[bh * NL + i_r0] = mq0 ? 0.0f : (__logf(lsum0) - esum0 / lsum0);
        outE[bh * NL + i_r1] = mq1 ? 0.0f : (__logf(lsum1) - esum1 / lsum1);
    }

    // ---- fused normalize + tail zero-fill (CTA owns its 128 A rows) ----
    __syncthreads();   // e-writes visible block-wide; also a global mem fence for own thread reads

    const int nk16 = nk * 16;             // float4 columns covered by tiles
    #pragma unroll 1
    for (int rr = 0; rr < 16; rr++) {
        const int row = i0 + w * 16 + rr;
        const float invr = __shfl_sync(0xffffffffu,
                                       (rr < 8) ? inv0 : inv1, (rr & 7) * 4);
        float4* Ar = (float4*)(outA + ((size_t)bh * NL + row) * NS);
        for (int c4 = lane; c4 < nk16; c4 += 32) {
            float4 x = Ar[c4];
            x.x *= invr; x.y *= invr; x.z *= invr; x.w *= invr;
            Ar[c4] = x;
        }
        for (int c4 = nk16 + lane; c4 < NS / 4; c4 += 32)
            Ar[c4] = z4;
    }
}

extern "C" void kernel_launch(void* const* d_in, const int* in_sizes, int n_in,
                              void* d_out, int out_size) {
    const float* q = (const float*)d_in[0];
    const float* k = (const float*)d_in[1];
    const float* v = (const float*)d_in[2];
    const void* mk = d_in[3];
    const void* mq = d_in[4];

    float* outV = (float*)d_out;
    float* outA = outV + (size_t)NB * NL * NH * NE;
    float* outE = outA + (size_t)NB * NH * NL * NS;

    cudaFuncSetAttribute(attn_mma_kernel,
                         cudaFuncAttributeMaxDynamicSharedMemorySize, SM_BYTES);

    mask_prep_kernel<<<1, 256>>>(mk, mq);
    prep_kernel<<<2048, 256>>>(k, v);
    attn_mma_kernel<<<NBH * NQT, 256, SM_BYTES>>>(q, outV, outA, outE);
}

// round 7
// speedup vs baseline: 1.1218x; 1.1218x over previous
#include <cuda_runtime.h>
#include <math.h>
#include <stdint.h>

#define NB 2
#define NL 2048
#define NS 2048
#define NH 8
#define NE 64
#define NBH 16
#define SCALE 0.125f
#define TQ 128
#define TN 64
#define NQT (NL / TQ)
#define NKT (NS / TN)

// ---------------- device scratch ----------------
__device__ __align__(16) uint8_t g_kf[NBH][NKT][2][8192];
__device__ __align__(16) uint8_t g_vf[NBH][NKT][2][8192];
__device__ unsigned char g_mk[NB * NS];
__device__ unsigned char g_mq[NB * NL];

// ---------------- helpers ----------------
__device__ __forceinline__ uint32_t bf16_bits(float x) {
    uint32_t fb = __float_as_uint(x);
    return (fb + 0x7fffu + ((fb >> 16) & 1u)) >> 16;
}
__device__ __forceinline__ float bf16_f(float x) {
    return __uint_as_float(bf16_bits(x) << 16);
}
__device__ __forceinline__ uint32_t packbf(float lo_elem, float hi_elem) {
    return bf16_bits(lo_elem) | (bf16_bits(hi_elem) << 16);
}
__device__ __forceinline__ uint32_t smem_u32(const void* p) {
    uint32_t a;
    asm("{ .reg .u64 t; cvta.to.shared.u64 t, %1; cvt.u32.u64 %0, t; }" : "=r"(a) : "l"(p));
    return a;
}
__device__ __forceinline__ void mma16816(float d[4], const uint32_t a[4],
                                         uint32_t b0, uint32_t b1) {
    asm volatile(
        "mma.sync.aligned.m16n8k16.row.col.f32.bf16.bf16.f32 "
        "{%0,%1,%2,%3},{%4,%5,%6,%7},{%8,%9},{%0,%1,%2,%3};"
        : "+f"(d[0]), "+f"(d[1]), "+f"(d[2]), "+f"(d[3])
        : "r"(a[0]), "r"(a[1]), "r"(a[2]), "r"(a[3]), "r"(b0), "r"(b1));
}
__device__ __forceinline__ void cpa16(uint32_t dst, const void* src) {
    asm volatile("cp.async.cg.shared.global [%0], [%1], 16;" :: "r"(dst), "l"(src));
}
#define CPA_COMMIT() asm volatile("cp.async.commit_group;" ::: "memory")
#define CPA_WAIT0()  asm volatile("cp.async.wait_group 0;" ::: "memory")
#define CPA_WAIT1()  asm volatile("cp.async.wait_group 1;" ::: "memory")

// ---------------- mask prep: 16 blocks, redundant dtype detection ----------------
__global__ __launch_bounds__(256) void mask_prep_kernel(const void* mk_raw, const void* mq_raw) {
    __shared__ int sh_f32, sh_u8;
    if (threadIdx.x == 0) { sh_f32 = 0; sh_u8 = 0; }
    __syncthreads();
    // detect over first 4096 bytes (valid for u8/i32/f32 layouts)
    const uint32_t* p32 = (const uint32_t*)mk_raw;
    int f32 = 0, u8 = 0;
    #pragma unroll
    for (int it = 0; it < 4; it++) {
        uint32_t wv = p32[it * 256 + threadIdx.x];
        if (((wv >> 24) & 0xff) == 0x3f) f32 = 1;
        if (wv & 0x00ffff00u) u8 = 1;
    }
    if (f32) atomicOr(&sh_f32, 1);
    if (u8) atomicOr(&sh_u8, 1);
    __syncthreads();
    int mode = sh_f32 ? 2 : (sh_u8 ? 1 : 0);

    int idx = blockIdx.x * 256 + threadIdx.x;   // one element per thread
    unsigned char vk, vq;
    if (mode == 2) { vk = ((const float*)mk_raw)[idx] != 0.0f; vq = ((const float*)mq_raw)[idx] != 0.0f; }
    else if (mode == 1) { vk = ((const unsigned char*)mk_raw)[idx] != 0; vq = ((const unsigned char*)mq_raw)[idx] != 0; }
    else { vk = ((const int*)mk_raw)[idx] != 0; vq = ((const int*)mq_raw)[idx] != 0; }
    g_mk[idx] = vk;
    g_mq[idx] = vq;
}

// ---------------- prep: fragment-ordered bf16 hi/lo split ----------------
__global__ __launch_bounds__(256) void prep_kernel(const float* __restrict__ k,
                                                   const float* __restrict__ v) {
    const int kind = blockIdx.x >> 10;                   // 0 = K, 1 = V^T
    const int c = ((blockIdx.x & 1023) << 8) + threadIdx.x;
    const int lane = c & 31;
    const int chunk = (c >> 5) & 1;
    const int bn = (c >> 6) & 7;
    const int kt = (c >> 9) & 31;
    const int bh = c >> 14;
    const int b = bh >> 3, h = bh & 7;
    const int c2 = lane & 3, trow = lane >> 2;

    uint32_t hi[4], lo[4];
    if (kind == 0) {
        const int j = kt * 64 + bn * 8 + trow;
        const float* base = k + ((size_t)(b * NS + j) * NH + h) * NE;
        #pragma unroll
        for (int kc_in = 0; kc_in < 2; kc_in++) {
            #pragma unroll
            for (int kh = 0; kh < 2; kh++) {
                int e = (chunk * 2 + kc_in) * 16 + kh * 8 + 2 * c2;
                float2 x = *(const float2*)(base + e);
                int idx = kc_in * 2 + kh;
                hi[idx] = packbf(x.x, x.y);
                lo[idx] = packbf(x.x - bf16_f(x.x), x.y - bf16_f(x.y));
            }
        }
        uint32_t off = bn * 1024 + chunk * 512 + lane * 16;
        *(uint4*)(&g_kf[bh][kt][0][off]) = make_uint4(hi[0], hi[1], hi[2], hi[3]);
        *(uint4*)(&g_kf[bh][kt][1][off]) = make_uint4(lo[0], lo[1], lo[2], lo[3]);
    } else {
        const int e = bn * 8 + trow;
        #pragma unroll
        for (int kc_in = 0; kc_in < 2; kc_in++) {
            #pragma unroll
            for (int kh = 0; kh < 2; kh++) {
                int jb = kt * 64 + (chunk * 2 + kc_in) * 16 + kh * 8 + 2 * c2;
                float x0 = v[((size_t)(b * NS + jb) * NH + h) * NE + e];
                float x1 = v[((size_t)(b * NS + jb + 1) * NH + h) * NE + e];
                int idx = kc_in * 2 + kh;
                hi[idx] = packbf(x0, x1);
                lo[idx] = packbf(x0 - bf16_f(x0), x1 - bf16_f(x1));
            }
        }
        uint32_t off = bn * 1024 + chunk * 512 + lane * 16;
        *(uint4*)(&g_vf[bh][kt][0][off]) = make_uint4(hi[0], hi[1], hi[2], hi[3]);
        *(uint4*)(&g_vf[bh][kt][1][off]) = make_uint4(lo[0], lo[1], lo[2], lo[3]);
    }
}

// ---------------- attention: 2-pass mma.sync bf16 flash, normalized A written once ----------------
#define SM_BYTES (65536 + 256)

__global__ __launch_bounds__(256, 1) void attn_mma_kernel(const float* __restrict__ q,
                                                          float* __restrict__ outV,
                                                          float* __restrict__ outA,
                                                          float* __restrict__ outE) {
    extern __shared__ __align__(16) char sm[];
    const int tid = threadIdx.x;
    const int w = tid >> 5;
    const int lane = tid & 31;
    const int c2 = lane & 3, trow = lane >> 2;

    const int qt = (NQT - 1) - (blockIdx.x >> 4);
    const int bh = blockIdx.x & 15;
    const int b = bh >> 3, h = bh & 7;
    const int i0 = qt * TQ;
    const int nk = 2 * qt + 2;

    const int i_r0 = i0 + w * 16 + trow;
    const int i_r1 = i_r0 + 8;
    const int i_wmax = i0 + w * 16 + 15;

    const uint32_t smb = smem_u32(sm);

    // Q fragments (hi/lo), register-resident
    uint32_t qh[4][4], ql[4][4];
    {
        const float* q0 = q + ((size_t)(b * NL + i_r0) * NH + h) * NE;
        const float* q1 = q + ((size_t)(b * NL + i_r1) * NH + h) * NE;
        #pragma unroll
        for (int kc = 0; kc < 4; kc++) {
            int e = kc * 16 + 2 * c2;
            float2 a0 = *(const float2*)(q0 + e);
            float2 a1 = *(const float2*)(q1 + e);
            float2 b0 = *(const float2*)(q0 + e + 8);
            float2 b1 = *(const float2*)(q1 + e + 8);
            qh[kc][0] = packbf(a0.x, a0.y); qh[kc][1] = packbf(a1.x, a1.y);
            qh[kc][2] = packbf(b0.x, b0.y); qh[kc][3] = packbf(b1.x, b1.y);
            ql[kc][0] = packbf(a0.x - bf16_f(a0.x), a0.y - bf16_f(a0.y));
            ql[kc][1] = packbf(a1.x - bf16_f(a1.x), a1.y - bf16_f(a1.y));
            ql[kc][2] = packbf(b0.x - bf16_f(b0.x), b0.y - bf16_f(b0.y));
            ql[kc][3] = packbf(b1.x - bf16_f(b1.x), b1.y - bf16_f(b1.y));
        }
    }

    float sacc[8][4];
    float oacc[8][4];
    #pragma unroll
    for (int bn = 0; bn < 8; bn++)
        #pragma unroll
        for (int u = 0; u < 4; u++) { sacc[bn][u] = 0.0f; oacc[bn][u] = 0.0f; }

    float lsum0 = 0.0f, lsum1 = 0.0f, esum0 = 0.0f, esum1 = 0.0f;
    float* Arow0 = outA + ((size_t)bh * NL + i_r0) * NS;
    float* Arow1 = outA + ((size_t)bh * NL + i_r1) * NS;

    auto stageKV = [&](int bufid, int kt) {
        const char* srcK = (const char*)g_kf[bh][kt];
        const char* srcV = (const char*)g_vf[bh][kt];
        uint32_t dst = smb + bufid * 32768;
        #pragma unroll
        for (int i = 0; i < 4; i++) {
            uint32_t off = (uint32_t)(i * 256 + tid) * 16;
            cpa16(dst + off, srcK + off);
            cpa16(dst + 16384 + off, srcV + off);
        }
        if (tid < 16)
            *(uint32_t*)(sm + 65536 + bufid * 64 + tid * 4) =
                *(const uint32_t*)(g_mk + b * NS + kt * 64 + tid * 4);
    };
    auto stageK = [&](int bufid, int kt) {
        const char* srcK = (const char*)g_kf[bh][kt];
        uint32_t dst = smb + bufid * 32768;
        #pragma unroll
        for (int i = 0; i < 4; i++) {
            uint32_t off = (uint32_t)(i * 256 + tid) * 16;
            cpa16(dst + off, srcK + off);
        }
        if (tid < 16)
            *(uint32_t*)(sm + 65536 + bufid * 64 + tid * 4) =
                *(const uint32_t*)(g_mk + b * NS + kt * 64 + tid * 4);
    };

    // ================= PASS 1: lsum/esum + AV (no A store) =================
    stageKV(0, 0);
    CPA_COMMIT();

    int buf = 0;
    for (int kt = 0; kt < nk; kt++) {
        if (kt + 1 < nk) { stageKV(buf ^ 1, kt + 1); CPA_COMMIT(); CPA_WAIT1(); }
        else CPA_WAIT0();
        __syncthreads();

        const int j0 = kt * TN;
        if (j0 <= i_wmax) {
            const char* bufp = sm + buf * 32768;
            const unsigned char* msk = (const unsigned char*)(sm + 65536 + buf * 64);

            // ---- QK: 3-pass bf16 ----
            #pragma unroll
            for (int bn = 0; bn < 8; bn++) {
                uint4 h0 = *(const uint4*)(bufp + bn * 1024 + lane * 16);
                uint4 h1 = *(const uint4*)(bufp + bn * 1024 + 512 + lane * 16);
                uint4 l0 = *(const uint4*)(bufp + 8192 + bn * 1024 + lane * 16);
                uint4 l1 = *(const uint4*)(bufp + 8192 + bn * 1024 + 512 + lane * 16);
                mma16816(sacc[bn], qh[0], h0.x, h0.y);
                mma16816(sacc[bn], qh[1], h0.z, h0.w);
                mma16816(sacc[bn], qh[2], h1.x, h1.y);
                mma16816(sacc[bn], qh[3], h1.z, h1.w);
                mma16816(sacc[bn], qh[0], l0.x, l0.y);
                mma16816(sacc[bn], qh[1], l0.z, l0.w);
                mma16816(sacc[bn], qh[2], l1.x, l1.y);
                mma16816(sacc[bn], qh[3], l1.z, l1.w);
                mma16816(sacc[bn], ql[0], h0.x, h0.y);
                mma16816(sacc[bn], ql[1], h0.z, h0.w);
                mma16816(sacc[bn], ql[2], h1.x, h1.y);
                mma16816(sacc[bn], ql[3], h1.z, h1.w);
            }

            // ---- epilogue: exp, sums, P frags (NO A store) ----
            uint32_t pa_hi[4][4], pa_lo[4][4];
            #pragma unroll
            for (int bn = 0; bn < 8; bn++) {
                int colb = j0 + bn * 8 + 2 * c2;
                float s00 = sacc[bn][0] * SCALE, s01 = sacc[bn][1] * SCALE;
                float s10 = sacc[bn][2] * SCALE, s11 = sacc[bn][3] * SCALE;
                unsigned char m0 = msk[bn * 8 + 2 * c2];
                unsigned char m1 = msk[bn * 8 + 2 * c2 + 1];
                float e00 = (m0 || colb > i_r0) ? 0.0f : __expf(s00);
                float e01 = (m1 || colb + 1 > i_r0) ? 0.0f : __expf(s01);
                float e10 = (m0 || colb > i_r1) ? 0.0f : __expf(s10);
                float e11 = (m1 || colb + 1 > i_r1) ? 0.0f : __expf(s11);
                lsum0 += e00 + e01; esum0 += e00 * s00 + e01 * s01;
                lsum1 += e10 + e11; esum1 += e10 * s10 + e11 * s11;
                int kc = bn >> 1, s0i = (bn & 1) * 2;
                pa_hi[kc][s0i + 0] = packbf(e00, e01);
                pa_hi[kc][s0i + 1] = packbf(e10, e11);
                pa_lo[kc][s0i + 0] = packbf(e00 - bf16_f(e00), e01 - bf16_f(e01));
                pa_lo[kc][s0i + 1] = packbf(e10 - bf16_f(e10), e11 - bf16_f(e11));
                sacc[bn][0] = 0.0f; sacc[bn][1] = 0.0f;
                sacc[bn][2] = 0.0f; sacc[bn][3] = 0.0f;
            }

            // ---- AV: 3-pass bf16 ----
            #pragma unroll
            for (int bn = 0; bn < 8; bn++) {
                uint4 h0 = *(const uint4*)(bufp + 16384 + bn * 1024 + lane * 16);
                uint4 h1 = *(const uint4*)(bufp + 16384 + bn * 1024 + 512 + lane * 16);
                uint4 l0 = *(const uint4*)(bufp + 24576 + bn * 1024 + lane * 16);
                uint4 l1 = *(const uint4*)(bufp + 24576 + bn * 1024 + 512 + lane * 16);
                mma16816(oacc[bn], pa_hi[0], h0.x, h0.y);
                mma16816(oacc[bn], pa_hi[1], h0.z, h0.w);
                mma16816(oacc[bn], pa_hi[2], h1.x, h1.y);
                mma16816(oacc[bn], pa_hi[3], h1.z, h1.w);
                mma16816(oacc[bn], pa_hi[0], l0.x, l0.y);
                mma16816(oacc[bn], pa_hi[1], l0.z, l0.w);
                mma16816(oacc[bn], pa_hi[2], l1.x, l1.y);
                mma16816(oacc[bn], pa_hi[3], l1.z, l1.w);
                mma16816(oacc[bn], pa_lo[0], h0.x, h0.y);
                mma16816(oacc[bn], pa_lo[1], h0.z, h0.w);
                mma16816(oacc[bn], pa_lo[2], h1.x, h1.y);
                mma16816(oacc[bn], pa_lo[3], h1.z, h1.w);
            }
        }
        buf ^= 1;
        __syncthreads();
    }

    // ---- stats: quad reduce, V write, entropy ----
    lsum0 += __shfl_xor_sync(0xffffffffu, lsum0, 1);
    lsum0 += __shfl_xor_sync(0xffffffffu, lsum0, 2);
    lsum1 += __shfl_xor_sync(0xffffffffu, lsum1, 1);
    lsum1 += __shfl_xor_sync(0xffffffffu, lsum1, 2);
    esum0 += __shfl_xor_sync(0xffffffffu, esum0, 1);
    esum0 += __shfl_xor_sync(0xffffffffu, esum0, 2);
    esum1 += __shfl_xor_sync(0xffffffffu, esum1, 1);
    esum1 += __shfl_xor_sync(0xffffffffu, esum1, 2);

    const bool mq0 = g_mq[b * NL + i_r0] != 0;
    const bool mq1 = g_mq[b * NL + i_r1] != 0;
    const float inv0 = mq0 ? 0.0f : 1.0f / lsum0;
    const float inv1 = mq1 ? 0.0f : 1.0f / lsum1;

    float* vo0 = outV + ((size_t)(b * NL + i_r0) * NH + h) * NE;
    float* vo1 = outV + ((size_t)(b * NL + i_r1) * NH + h) * NE;
    #pragma unroll
    for (int bn = 0; bn < 8; bn++) {
        int e0 = bn * 8 + 2 * c2;
        *(float2*)(vo0 + e0) = make_float2(oacc[bn][0] * inv0, oacc[bn][1] * inv0);
        *(float2*)(vo1 + e0) = make_float2(oacc[bn][2] * inv1, oacc[bn][3] * inv1);
    }
    if (c2 == 0) {
        outE[bh * NL + i_r0] = mq0 ? 0.0f : (__logf(lsum0) - esum0 / lsum0);
        outE[bh * NL + i_r1] = mq1 ? 0.0f : (__logf(lsum1) - esum1 / lsum1);
    }

    const float4 z4 = make_float4(0, 0, 0, 0);

    // ---- column tail zero-fill (j >= nk*64) ----
    {
        const int nk16 = nk * 16;
        #pragma unroll 1
        for (int rr = 0; rr < 16; rr++) {
            const int row = i0 + w * 16 + rr;
            float4* Ar = (float4*)(outA + ((size_t)bh * NL + row) * NS);
            for (int c4 = nk16 + lane; c4 < NS / 4; c4 += 32)
                Ar[c4] = z4;
        }
    }

    // ================= PASS 2: recompute scores, write normalized A =================
    __syncthreads();
    stageK(0, 0);
    CPA_COMMIT();

    buf = 0;
    for (int kt = 0; kt < nk; kt++) {
        if (kt + 1 < nk) { stageK(buf ^ 1, kt + 1); CPA_COMMIT(); CPA_WAIT1(); }
        else CPA_WAIT0();
        __syncthreads();

        const int j0 = kt * TN;
        if (j0 <= i_wmax) {
            const char* bufp = sm + buf * 32768;
            const unsigned char* msk = (const unsigned char*)(sm + 65536 + buf * 64);

            #pragma unroll
            for (int bn = 0; bn < 8; bn++) {
                uint4 h0 = *(const uint4*)(bufp + bn * 1024 + lane * 16);
                uint4 h1 = *(const uint4*)(bufp + bn * 1024 + 512 + lane * 16);
                uint4 l0 = *(const uint4*)(bufp + 8192 + bn * 1024 + lane * 16);
                uint4 l1 = *(const uint4*)(bufp + 8192 + bn * 1024 + 512 + lane * 16);
                mma16816(sacc[bn], qh[0], h0.x, h0.y);
                mma16816(sacc[bn], qh[1], h0.z, h0.w);
                mma16816(sacc[bn], qh[2], h1.x, h1.y);
                mma16816(sacc[bn], qh[3], h1.z, h1.w);
                mma16816(sacc[bn], qh[0], l0.x, l0.y);
                mma16816(sacc[bn], qh[1], l0.z, l0.w);
                mma16816(sacc[bn], qh[2], l1.x, l1.y);
                mma16816(sacc[bn], qh[3], l1.z, l1.w);
                mma16816(sacc[bn], ql[0], h0.x, h0.y);
                mma16816(sacc[bn], ql[1], h0.z, h0.w);
                mma16816(sacc[bn], ql[2], h1.x, h1.y);
                mma16816(sacc[bn], ql[3], h1.z, h1.w);
            }

            #pragma unroll
            for (int bn = 0; bn < 8; bn++) {
                int colb = j0 + bn * 8 + 2 * c2;
                float s00 = sacc[bn][0] * SCALE, s01 = sacc[bn][1] * SCALE;
                float s10 = sacc[bn][2] * SCALE, s11 = sacc[bn][3] * SCALE;
                unsigned char m0 = msk[bn * 8 + 2 * c2];
                unsigned char m1 = msk[bn * 8 + 2 * c2 + 1];
                float a00 = (m0 || colb > i_r0) ? 0.0f : __expf(s00) * inv0;
                float a01 = (m1 || colb + 1 > i_r0) ? 0.0f : __expf(s01) * inv0;
                float a10 = (m0 || colb > i_r1) ? 0.0f : __expf(s10) * inv1;
                float a11 = (m1 || colb + 1 > i_r1) ? 0.0f : __expf(s11) * inv1;
                *(float2*)(Arow0 + colb) = make_float2(a00, a01);
                *(float2*)(Arow1 + colb) = make_float2(a10, a11);
                sacc[bn][0] = 0.0f; sacc[bn][1] = 0.0f;
                sacc[bn][2] = 0.0f; sacc[bn][3] = 0.0f;
            }
        } else {
            // above-diagonal warp tile: zeros
            #pragma unroll
            for (int rr = 0; rr < 2; rr++) {
                float* Ar = (rr == 0 ? Arow0 : Arow1) + j0;
                #pragma unroll
                for (int u = 0; u < 4; u++)
                    ((float4*)Ar)[c2 * 4 + u] = z4;
            }
        }
        buf ^= 1;
        __syncthreads();
    }
}

extern "C" void kernel_launch(void* const* d_in, const int* in_sizes, int n_in,
                              void* d_out, int out_size) {
    const float* q = (const float*)d_in[0];
    const float* k = (const float*)d_in[1];
    const float* v = (const float*)d_in[2];
    const void* mk = d_in[3];
    const void* mq = d_in[4];

    float* outV = (float*)d_out;
    float* outA = outV + (size_t)NB * NL * NH * NE;
    float* outE = outA + (size_t)NB * NH * NL * NS;

    cudaFuncSetAttribute(attn_mma_kernel,
                         cudaFuncAttributeMaxDynamicSharedMemorySize, SM_BYTES);

    mask_prep_kernel<<<16, 256>>>(mk, mq);
    prep_kernel<<<2048, 256>>>(k, v);
    attn_mma_kernel<<<NBH * NQT, 256, SM_BYTES>>>(q, outV, outA, outE);
}

// round 9
// speedup vs baseline: 1.1882x; 1.0592x over previous
#include <cuda_runtime.h>
#include <math.h>
#include <stdint.h>

#define NB 2
#define NL 2048
#define NS 2048
#define NH 8
#define NE 64
#define NBH 16
#define SCALE 0.125f
#define TQ 128
#define TN 64
#define NQT (NL / TQ)
#define NKT (NS / TN)

// ---------------- device scratch ----------------
__device__ __align__(16) uint8_t g_kf[NBH][NKT][2][8192];
__device__ __align__(16) uint8_t g_vf[NBH][NKT][2][8192];
__device__ unsigned char g_mk[NB * NS];
__device__ unsigned char g_mq[NB * NL];

// ---------------- helpers ----------------
// pack two f32 -> bf16x2 (rn-even), hi goes to bits[31:16]
__device__ __forceinline__ uint32_t cvt_bf16x2(float hi, float lo) {
    uint32_t r;
    asm("cvt.rn.bf16x2.f32 %0, %1, %2;" : "=r"(r) : "f"(hi), "f"(lo));
    return r;
}
__device__ __forceinline__ float lo_f(uint32_t p) { return __uint_as_float(p << 16); }
__device__ __forceinline__ float hi_f(uint32_t p) { return __uint_as_float(p & 0xffff0000u); }

__device__ __forceinline__ uint32_t smem_u32(const void* p) {
    uint32_t a;
    asm("{ .reg .u64 t; cvta.to.shared.u64 t, %1; cvt.u32.u64 %0, t; }" : "=r"(a) : "l"(p));
    return a;
}
__device__ __forceinline__ void mma16816(float d[4], const uint32_t a[4],
                                         uint32_t b0, uint32_t b1) {
    asm volatile(
        "mma.sync.aligned.m16n8k16.row.col.f32.bf16.bf16.f32 "
        "{%0,%1,%2,%3},{%4,%5,%6,%7},{%8,%9},{%0,%1,%2,%3};"
        : "+f"(d[0]), "+f"(d[1]), "+f"(d[2]), "+f"(d[3])
        : "r"(a[0]), "r"(a[1]), "r"(a[2]), "r"(a[3]), "r"(b0), "r"(b1));
}
__device__ __forceinline__ void cpa16(uint32_t dst, const void* src) {
    asm volatile("cp.async.cg.shared.global [%0], [%1], 16;" :: "r"(dst), "l"(src));
}
#define CPA_COMMIT() asm volatile("cp.async.commit_group;" ::: "memory")
#define CPA_WAIT0()  asm volatile("cp.async.wait_group 0;" ::: "memory")
#define CPA_WAIT1()  asm volatile("cp.async.wait_group 1;" ::: "memory")

// ---------------- prep: bf16 hi/lo fragment tiles + mask normalization ----------------
// blocks [0,1024): K, [1024,2048): V^T, [2048,2064): masks
__global__ __launch_bounds__(256) void prep_kernel(const float* __restrict__ k,
                                                   const float* __restrict__ v,
                                                   const void* mk_raw,
                                                   const void* mq_raw) {
    if (blockIdx.x >= 2048) {
        // ---- mask path: dtype detect over first 4096 bytes, then normalize ----
        __shared__ int sh_f32, sh_u8;
        if (threadIdx.x == 0) { sh_f32 = 0; sh_u8 = 0; }
        __syncthreads();
        const uint32_t* p32 = (const uint32_t*)mk_raw;
        int f32 = 0, u8 = 0;
        #pragma unroll
        for (int it = 0; it < 4; it++) {
            uint32_t wv = p32[it * 256 + threadIdx.x];
            if (((wv >> 24) & 0xff) == 0x3f) f32 = 1;
            if (wv & 0x00ffff00u) u8 = 1;
        }
        if (f32) atomicOr(&sh_f32, 1);
        if (u8) atomicOr(&sh_u8, 1);
        __syncthreads();
        int mode = sh_f32 ? 2 : (sh_u8 ? 1 : 0);
        int idx = (blockIdx.x - 2048) * 256 + threadIdx.x;
        unsigned char vk, vq;
        if (mode == 2) { vk = ((const float*)mk_raw)[idx] != 0.0f; vq = ((const float*)mq_raw)[idx] != 0.0f; }
        else if (mode == 1) { vk = ((const unsigned char*)mk_raw)[idx] != 0; vq = ((const unsigned char*)mq_raw)[idx] != 0; }
        else { vk = ((const int*)mk_raw)[idx] != 0; vq = ((const int*)mq_raw)[idx] != 0; }
        g_mk[idx] = vk;
        g_mq[idx] = vq;
        return;
    }

    const int kind = blockIdx.x >> 10;                   // 0 = K, 1 = V^T
    const int c = ((blockIdx.x & 1023) << 8) + threadIdx.x;
    const int lane = c & 31;
    const int chunk = (c >> 5) & 1;
    const int bn = (c >> 6) & 7;
    const int kt = (c >> 9) & 31;
    const int bh = c >> 14;
    const int b = bh >> 3, h = bh & 7;
    const int c2 = lane & 3, trow = lane >> 2;

    uint32_t hi[4], lo[4];
    if (kind == 0) {
        const int j = kt * 64 + bn * 8 + trow;
        const float* base = k + ((size_t)(b * NS + j) * NH + h) * NE;
        #pragma unroll
        for (int kc_in = 0; kc_in < 2; kc_in++) {
            #pragma unroll
            for (int kh = 0; kh < 2; kh++) {
                int e = (chunk * 2 + kc_in) * 16 + kh * 8 + 2 * c2;
                float2 x = *(const float2*)(base + e);
                int idx = kc_in * 2 + kh;
                uint32_t hp = cvt_bf16x2(x.y, x.x);
                hi[idx] = hp;
                lo[idx] = cvt_bf16x2(x.y - hi_f(hp), x.x - lo_f(hp));
            }
        }
        uint32_t off = bn * 1024 + chunk * 512 + lane * 16;
        *(uint4*)(&g_kf[bh][kt][0][off]) = make_uint4(hi[0], hi[1], hi[2], hi[3]);
        *(uint4*)(&g_kf[bh][kt][1][off]) = make_uint4(lo[0], lo[1], lo[2], lo[3]);
    } else {
        const int e = bn * 8 + trow;
        #pragma unroll
        for (int kc_in = 0; kc_in < 2; kc_in++) {
            #pragma unroll
            for (int kh = 0; kh < 2; kh++) {
                int jb = kt * 64 + (chunk * 2 + kc_in) * 16 + kh * 8 + 2 * c2;
                float x0 = v[((size_t)(b * NS + jb) * NH + h) * NE + e];
                float x1 = v[((size_t)(b * NS + jb + 1) * NH + h) * NE + e];
                int idx = kc_in * 2 + kh;
                uint32_t hp = cvt_bf16x2(x1, x0);
                hi[idx] = hp;
                lo[idx] = cvt_bf16x2(x1 - hi_f(hp), x0 - lo_f(hp));
            }
        }
        uint32_t off = bn * 1024 + chunk * 512 + lane * 16;
        *(uint4*)(&g_vf[bh][kt][0][off]) = make_uint4(hi[0], hi[1], hi[2], hi[3]);
        *(uint4*)(&g_vf[bh][kt][1][off]) = make_uint4(lo[0], lo[1], lo[2], lo[3]);
    }
}

// ---------------- attention: 2-pass mma.sync bf16 flash ----------------
#define SM_BYTES (65536 + 256)

__global__ __launch_bounds__(256, 1) void attn_mma_kernel(const float* __restrict__ q,
                                                          float* __restrict__ outV,
                                                          float* __restrict__ outA,
                                                          float* __restrict__ outE) {
    extern __shared__ __align__(16) char sm[];
    const int tid = threadIdx.x;
    const int w = tid >> 5;
    const int lane = tid & 31;
    const int c2 = lane & 3, trow = lane >> 2;

    const int qt = (NQT - 1) - (blockIdx.x >> 4);
    const int bh = blockIdx.x & 15;
    const int b = bh >> 3, h = bh & 7;
    const int i0 = qt * TQ;
    const int nk = 2 * qt + 2;

    const int i_r0 = i0 + w * 16 + trow;
    const int i_r1 = i_r0 + 8;
    const int i_wmax = i0 + w * 16 + 15;

    const uint32_t smb = smem_u32(sm);

    // Q fragments (hi/lo), SCALE pre-folded (exact: power-of-2)
    uint32_t qh[4][4], ql[4][4];
    {
        const float* q0 = q + ((size_t)(b * NL + i_r0) * NH + h) * NE;
        const float* q1 = q + ((size_t)(b * NL + i_r1) * NH + h) * NE;
        #pragma unroll
        for (int kc = 0; kc < 4; kc++) {
            int e = kc * 16 + 2 * c2;
            float2 a0 = *(const float2*)(q0 + e);
            float2 a1 = *(const float2*)(q1 + e);
            float2 b0 = *(const float2*)(q0 + e + 8);
            float2 b1 = *(const float2*)(q1 + e + 8);
            a0.x *= SCALE; a0.y *= SCALE; a1.x *= SCALE; a1.y *= SCALE;
            b0.x *= SCALE; b0.y *= SCALE; b1.x *= SCALE; b1.y *= SCALE;
            uint32_t p0 = cvt_bf16x2(a0.y, a0.x);
            uint32_t p1 = cvt_bf16x2(a1.y, a1.x);
            uint32_t p2 = cvt_bf16x2(b0.y, b0.x);
            uint32_t p3 = cvt_bf16x2(b1.y, b1.x);
            qh[kc][0] = p0; qh[kc][1] = p1; qh[kc][2] = p2; qh[kc][3] = p3;
            ql[kc][0] = cvt_bf16x2(a0.y - hi_f(p0), a0.x - lo_f(p0));
            ql[kc][1] = cvt_bf16x2(a1.y - hi_f(p1), a1.x - lo_f(p1));
            ql[kc][2] = cvt_bf16x2(b0.y - hi_f(p2), b0.x - lo_f(p2));
            ql[kc][3] = cvt_bf16x2(b1.y - hi_f(p3), b1.x - lo_f(p3));
        }
    }

    float sacc[8][4];
    float oacc[8][4];
    #pragma unroll
    for (int bn = 0; bn < 8; bn++)
        #pragma unroll
        for (int u = 0; u < 4; u++) { sacc[bn][u] = 0.0f; oacc[bn][u] = 0.0f; }

    float lsum0 = 0.0f, lsum1 = 0.0f, esum0 = 0.0f, esum1 = 0.0f;
    float* Arow0 = outA + ((size_t)bh * NL + i_r0) * NS;
    float* Arow1 = outA + ((size_t)bh * NL + i_r1) * NS;

    auto stageKV = [&](int bufid, int kt) {
        const char* srcK = (const char*)g_kf[bh][kt];
        const char* srcV = (const char*)g_vf[bh][kt];
        uint32_t dst = smb + bufid * 32768;
        #pragma unroll
        for (int i = 0; i < 4; i++) {
            uint32_t off = (uint32_t)(i * 256 + tid) * 16;
            cpa16(dst + off, srcK + off);
            cpa16(dst + 16384 + off, srcV + off);
        }
        if (tid < 16)
            *(uint32_t*)(sm + 65536 + bufid * 64 + tid * 4) =
                *(const uint32_t*)(g_mk + b * NS + kt * 64 + tid * 4);
    };
    auto stageK = [&](int bufid, int kt) {
        const char* srcK = (const char*)g_kf[bh][kt];
        uint32_t dst = smb + bufid * 32768;
        #pragma unroll
        for (int i = 0; i < 4; i++) {
            uint32_t off = (uint32_t)(i * 256 + tid) * 16;
            cpa16(dst + off, srcK + off);
        }
        if (tid < 16)
            *(uint32_t*)(sm + 65536 + bufid * 64 + tid * 4) =
                *(const uint32_t*)(g_mk + b * NS + kt * 64 + tid * 4);
    };

    // ================= PASS 1: lsum/esum + AV (no A store) =================
    stageKV(0, 0);
    CPA_COMMIT();

    int buf = 0;
    for (int kt = 0; kt < nk; kt++) {
        if (kt + 1 < nk) { stageKV(buf ^ 1, kt + 1); CPA_COMMIT(); CPA_WAIT1(); }
        else CPA_WAIT0();
        __syncthreads();

        const int j0 = kt * TN;
        if (j0 <= i_wmax) {
            const char* bufp = sm + buf * 32768;
            const unsigned char* msk = (const unsigned char*)(sm + 65536 + buf * 64);

            // ---- QK: 3-pass bf16 ----
            #pragma unroll
            for (int bn = 0; bn < 8; bn++) {
                uint4 h0 = *(const uint4*)(bufp + bn * 1024 + lane * 16);
                uint4 h1 = *(const uint4*)(bufp + bn * 1024 + 512 + lane * 16);
                uint4 l0 = *(const uint4*)(bufp + 8192 + bn * 1024 + lane * 16);
                uint4 l1 = *(const uint4*)(bufp + 8192 + bn * 1024 + 512 + lane * 16);
                mma16816(sacc[bn], qh[0], h0.x, h0.y);
                mma16816(sacc[bn], qh[1], h0.z, h0.w);
                mma16816(sacc[bn], qh[2], h1.x, h1.y);
                mma16816(sacc[bn], qh[3], h1.z, h1.w);
                mma16816(sacc[bn], qh[0], l0.x, l0.y);
                mma16816(sacc[bn], qh[1], l0.z, l0.w);
                mma16816(sacc[bn], qh[2], l1.x, l1.y);
                mma16816(sacc[bn], qh[3], l1.z, l1.w);
                mma16816(sacc[bn], ql[0], h0.x, h0.y);
                mma16816(sacc[bn], ql[1], h0.z, h0.w);
                mma16816(sacc[bn], ql[2], h1.x, h1.y);
                mma16816(sacc[bn], ql[3], h1.z, h1.w);
            }

            // ---- epilogue: exp, sums, P frags (hardware bf16x2 packing) ----
            uint32_t pa_hi[4][4], pa_lo[4][4];
            #pragma unroll
            for (int bn = 0; bn < 8; bn++) {
                int colb = j0 + bn * 8 + 2 * c2;
                float s00 = sacc[bn][0], s01 = sacc[bn][1];
                float s10 = sacc[bn][2], s11 = sacc[bn][3];
                unsigned char m0 = msk[bn * 8 + 2 * c2];
                unsigned char m1 = msk[bn * 8 + 2 * c2 + 1];
                float e00 = (m0 || colb > i_r0) ? 0.0f : __expf(s00);
                float e01 = (m1 || colb + 1 > i_r0) ? 0.0f : __expf(s01);
                float e10 = (m0 || colb > i_r1) ? 0.0f : __expf(s10);
                float e11 = (m1 || colb + 1 > i_r1) ? 0.0f : __expf(s11);
                lsum0 += e00 + e01; esum0 += e00 * s00 + e01 * s01;
                lsum1 += e10 + e11; esum1 += e10 * s10 + e11 * s11;
                int kc = bn >> 1, s0i = (bn & 1) * 2;
                uint32_t h0 = cvt_bf16x2(e01, e00);
                uint32_t h1 = cvt_bf16x2(e11, e10);
                pa_hi[kc][s0i + 0] = h0;
                pa_hi[kc][s0i + 1] = h1;
                pa_lo[kc][s0i + 0] = cvt_bf16x2(e01 - hi_f(h0), e00 - lo_f(h0));
                pa_lo[kc][s0i + 1] = cvt_bf16x2(e11 - hi_f(h1), e10 - lo_f(h1));
                sacc[bn][0] = 0.0f; sacc[bn][1] = 0.0f;
                sacc[bn][2] = 0.0f; sacc[bn][3] = 0.0f;
            }

            // ---- AV: 3-pass bf16 ----
            #pragma unroll
            for (int bn = 0; bn < 8; bn++) {
                uint4 h0 = *(const uint4*)(bufp + 16384 + bn * 1024 + lane * 16);
                uint4 h1 = *(const uint4*)(bufp + 16384 + bn * 1024 + 512 + lane * 16);
                uint4 l0 = *(const uint4*)(bufp + 24576 + bn * 1024 + lane * 16);
                uint4 l1 = *(const uint4*)(bufp + 24576 + bn * 1024 + 512 + lane * 16);
                mma16816(oacc[bn], pa_hi[0], h0.x, h0.y);
                mma16816(oacc[bn], pa_hi[1], h0.z, h0.w);
                mma16816(oacc[bn], pa_hi[2], h1.x, h1.y);
                mma16816(oacc[bn], pa_hi[3], h1.z, h1.w);
                mma16816(oacc[bn], pa_hi[0], l0.x, l0.y);
                mma16816(oacc[bn], pa_hi[1], l0.z, l0.w);
                mma16816(oacc[bn], pa_hi[2], l1.x, l1.y);
                mma16816(oacc[bn], pa_hi[3], l1.z, l1.w);
                mma16816(oacc[bn], pa_lo[0], h0.x, h0.y);
                mma16816(oacc[bn], pa_lo[1], h0.z, h0.w);
                mma16816(oacc[bn], pa_lo[2], h1.x, h1.y);
                mma16816(oacc[bn], pa_lo[3], h1.z, h1.w);
            }
        }
        buf ^= 1;
        __syncthreads();
    }

    // ---- stats: quad reduce, V write, entropy ----
    lsum0 += __shfl_xor_sync(0xffffffffu, lsum0, 1);
    lsum0 += __shfl_xor_sync(0xffffffffu, lsum0, 2);
    lsum1 += __shfl_xor_sync(0xffffffffu, lsum1, 1);
    lsum1 += __shfl_xor_sync(0xffffffffu, lsum1, 2);
    esum0 += __shfl_xor_sync(0xffffffffu, esum0, 1);
    esum0 += __shfl_xor_sync(0xffffffffu, esum0, 2);
    esum1 += __shfl_xor_sync(0xffffffffu, esum1, 1);
    esum1 += __shfl_xor_sync(0xffffffffu, esum1, 2);

    const bool mq0 = g_mq[b * NL + i_r0] != 0;
    const bool mq1 = g_mq[b * NL + i_r1] != 0;
    const float inv0 = mq0 ? 0.0f : 1.0f / lsum0;
    const float inv1 = mq1 ? 0.0f : 1.0f / lsum1;

    float* vo0 = outV + ((size_t)(b * NL + i_r0) * NH + h) * NE;
    float* vo1 = outV + ((size_t)(b * NL + i_r1) * NH + h) * NE;
    #pragma unroll
    for (int bn = 0; bn < 8; bn++) {
        int e0 = bn * 8 + 2 * c2;
        *(float2*)(vo0 + e0) = make_float2(oacc[bn][0] * inv0, oacc[bn][1] * inv0);
        *(float2*)(vo1 + e0) = make_float2(oacc[bn][2] * inv1, oacc[bn][3] * inv1);
    }
    if (c2 == 0) {
        outE[bh * NL + i_r0] = mq0 ? 0.0f : (__logf(lsum0) - esum0 / lsum0);
        outE[bh * NL + i_r1] = mq1 ? 0.0f : (__logf(lsum1) - esum1 / lsum1);
    }

    const float4 z4 = make_float4(0, 0, 0, 0);

    // ---- column tail zero-fill (j >= nk*64) ----
    {
        const int nk16 = nk * 16;
        #pragma unroll 1
        for (int rr = 0; rr < 16; rr++) {
            const int row = i0 + w * 16 + rr;
            float4* Ar = (float4*)(outA + ((size_t)bh * NL + row) * NS);
            for (int c4 = nk16 + lane; c4 < NS / 4; c4 += 32)
                Ar[c4] = z4;
        }
    }

    // ================= PASS 2: recompute scores, write normalized A =================
    __syncthreads();
    stageK(0, 0);
    CPA_COMMIT();

    buf = 0;
    for (int kt = 0; kt < nk; kt++) {
        if (kt + 1 < nk) { stageK(buf ^ 1, kt + 1); CPA_COMMIT(); CPA_WAIT1(); }
        else CPA_WAIT0();
        __syncthreads();

        const int j0 = kt * TN;
        if (j0 <= i_wmax) {
            const char* bufp = sm + buf * 32768;
            const unsigned char* msk = (const unsigned char*)(sm + 65536 + buf * 64);

            #pragma unroll
            for (int bn = 0; bn < 8; bn++) {
                uint4 h0 = *(const uint4*)(bufp + bn * 1024 + lane * 16);
                uint4 h1 = *(const uint4*)(bufp + bn * 1024 + 512 + lane * 16);
                uint4 l0 = *(const uint4*)(bufp + 8192 + bn * 1024 + lane * 16);
                uint4 l1 = *(const uint4*)(bufp + 8192 + bn * 1024 + 512 + lane * 16);
                mma16816(sacc[bn], qh[0], h0.x, h0.y);
                mma16816(sacc[bn], qh[1], h0.z, h0.w);
                mma16816(sacc[bn], qh[2], h1.x, h1.y);
                mma16816(sacc[bn], qh[3], h1.z, h1.w);
                mma16816(sacc[bn], qh[0], l0.x, l0.y);
                mma16816(sacc[bn], qh[1], l0.z, l0.w);
                mma16816(sacc[bn], qh[2], l1.x, l1.y);
                mma16816(sacc[bn], qh[3], l1.z, l1.w);
                mma16816(sacc[bn], ql[0], h0.x, h0.y);
                mma16816(sacc[bn], ql[1], h0.z, h0.w);
                mma16816(sacc[bn], ql[2], h1.x, h1.y);
                mma16816(sacc[bn], ql[3], h1.z, h1.w);
            }

            #pragma unroll
            for (int bn = 0; bn < 8; bn++) {
                int colb = j0 + bn * 8 + 2 * c2;
                float s00 = sacc[bn][0], s01 = sacc[bn][1];
                float s10 = sacc[bn][2], s11 = sacc[bn][3];
                unsigned char m0 = msk[bn * 8 + 2 * c2];
                unsigned char m1 = msk[bn * 8 + 2 * c2 + 1];
                float a00 = (m0 || colb > i_r0) ? 0.0f : __expf(s00) * inv0;
                float a01 = (m1 || colb + 1 > i_r0) ? 0.0f : __expf(s01) * inv0;
                float a10 = (m0 || colb > i_r1) ? 0.0f : __expf(s10) * inv1;
                float a11 = (m1 || colb + 1 > i_r1) ? 0.0f : __expf(s11) * inv1;
                *(float2*)(Arow0 + colb) = make_float2(a00, a01);
                *(float2*)(Arow1 + colb) = make_float2(a10, a11);
                sacc[bn][0] = 0.0f; sacc[bn][1] = 0.0f;
                sacc[bn][2] = 0.0f; sacc[bn][3] = 0.0f;
            }
        } else {
            // above-diagonal warp tile: zeros
            #pragma unroll
            for (int rr = 0; rr < 2; rr++) {
                float* Ar = (rr == 0 ? Arow0 : Arow1) + j0;
                #pragma unroll
                for (int u = 0; u < 4; u++)
                    ((float4*)Ar)[c2 * 4 + u] = z4;
            }
        }
        buf ^= 1;
        __syncthreads();
    }
}

extern "C" void kernel_launch(void* const* d_in, const int* in_sizes, int n_in,
                              void* d_out, int out_size) {
    const float* q = (const float*)d_in[0];
    const float* k = (const float*)d_in[1];
    const float* v = (const float*)d_in[2];
    const void* mk = d_in[3];
    const void* mq = d_in[4];

    float* outV = (float*)d_out;
    float* outA = outV + (size_t)NB * NL * NH * NE;
    float* outE = outA + (size_t)NB * NH * NL * NS;

    cudaFuncSetAttribute(attn_mma_kernel,
                         cudaFuncAttributeMaxDynamicSharedMemorySize, SM_BYTES);

    prep_kernel<<<2064, 256>>>(k, v, mk, mq);
    attn_mma_kernel<<<NBH * NQT, 256, SM_BYTES>>>(q, outV, outA, outE);
}

// round 10
// speedup vs baseline: 1.4250x; 1.1993x over previous
#include <cuda_runtime.h>
#include <cuda_fp16.h>
#include <math.h>
#include <stdint.h>

#define NB 2
#define NL 2048
#define NS 2048
#define NH 8
#define NE 64
#define NBH 16
#define SCALE 0.125f
#define TQ 128
#define TN 64
#define NQT (NL / TQ)
#define NKT (NS / TN)

// ---------------- device scratch (single fp16 tiles now) ----------------
__device__ __align__(16) uint8_t g_kf[NBH][NKT][8192];
__device__ __align__(16) uint8_t g_vf[NBH][NKT][8192];
__device__ unsigned char g_mk[NB * NS];
__device__ unsigned char g_mq[NB * NL];

// ---------------- helpers ----------------
// pack two f32 -> f16x2 (rn), 'hi' into bits[31:16]
__device__ __forceinline__ uint32_t cvt_f16x2(float hi, float lo) {
    uint32_t r;
    asm("cvt.rn.f16x2.f32 %0, %1, %2;" : "=r"(r) : "f"(hi), "f"(lo));
    return r;
}
__device__ __forceinline__ float2 unpack_f16x2(uint32_t p) {
    __half2 h = *reinterpret_cast<__half2*>(&p);
    return __half22float2(h);          // .x = lo half, .y = hi half
}
__device__ __forceinline__ uint32_t smem_u32(const void* p) {
    uint32_t a;
    asm("{ .reg .u64 t; cvta.to.shared.u64 t, %1; cvt.u32.u64 %0, t; }" : "=r"(a) : "l"(p));
    return a;
}
__device__ __forceinline__ void mma16816(float d[4], const uint32_t a[4],
                                         uint32_t b0, uint32_t b1) {
    asm volatile(
        "mma.sync.aligned.m16n8k16.row.col.f32.f16.f16.f32 "
        "{%0,%1,%2,%3},{%4,%5,%6,%7},{%8,%9},{%0,%1,%2,%3};"
        : "+f"(d[0]), "+f"(d[1]), "+f"(d[2]), "+f"(d[3])
        : "r"(a[0]), "r"(a[1]), "r"(a[2]), "r"(a[3]), "r"(b0), "r"(b1));
}
__device__ __forceinline__ void cpa16(uint32_t dst, const void* src) {
    asm volatile("cp.async.cg.shared.global [%0], [%1], 16;" :: "r"(dst), "l"(src));
}
#define CPA_COMMIT() asm volatile("cp.async.commit_group;" ::: "memory")
#define CPA_WAIT0()  asm volatile("cp.async.wait_group 0;" ::: "memory")
#define CPA_WAIT1()  asm volatile("cp.async.wait_group 1;" ::: "memory")

// ---------------- prep: fp16 fragment tiles + mask normalization ----------------
// blocks [0,1024): K, [1024,2048): V^T, [2048,2064): masks
__global__ __launch_bounds__(256) void prep_kernel(const float* __restrict__ k,
                                                   const float* __restrict__ v,
                                                   const void* mk_raw,
                                                   const void* mq_raw) {
    if (blockIdx.x >= 2048) {
        __shared__ int sh_f32, sh_u8;
        if (threadIdx.x == 0) { sh_f32 = 0; sh_u8 = 0; }
        __syncthreads();
        const uint32_t* p32 = (const uint32_t*)mk_raw;
        int f32 = 0, u8 = 0;
        #pragma unroll
        for (int it = 0; it < 4; it++) {
            uint32_t wv = p32[it * 256 + threadIdx.x];
            if (((wv >> 24) & 0xff) == 0x3f) f32 = 1;
            if (wv & 0x00ffff00u) u8 = 1;
        }
        if (f32) atomicOr(&sh_f32, 1);
        if (u8) atomicOr(&sh_u8, 1);
        __syncthreads();
        int mode = sh_f32 ? 2 : (sh_u8 ? 1 : 0);
        int idx = (blockIdx.x - 2048) * 256 + threadIdx.x;
        unsigned char vk, vq;
        if (mode == 2) { vk = ((const float*)mk_raw)[idx] != 0.0f; vq = ((const float*)mq_raw)[idx] != 0.0f; }
        else if (mode == 1) { vk = ((const unsigned char*)mk_raw)[idx] != 0; vq = ((const unsigned char*)mq_raw)[idx] != 0; }
        else { vk = ((const int*)mk_raw)[idx] != 0; vq = ((const int*)mq_raw)[idx] != 0; }
        g_mk[idx] = vk;
        g_mq[idx] = vq;
        return;
    }

    const int kind = blockIdx.x >> 10;                   // 0 = K, 1 = V^T
    const int c = ((blockIdx.x & 1023) << 8) + threadIdx.x;
    const int lane = c & 31;
    const int chunk = (c >> 5) & 1;
    const int bn = (c >> 6) & 7;
    const int kt = (c >> 9) & 31;
    const int bh = c >> 14;
    const int b = bh >> 3, h = bh & 7;
    const int c2 = lane & 3, trow = lane >> 2;

    uint32_t hp[4];
    if (kind == 0) {
        const int j = kt * 64 + bn * 8 + trow;
        const float* base = k + ((size_t)(b * NS + j) * NH + h) * NE;
        #pragma unroll
        for (int kc_in = 0; kc_in < 2; kc_in++) {
            #pragma unroll
            for (int kh = 0; kh < 2; kh++) {
                int e = (chunk * 2 + kc_in) * 16 + kh * 8 + 2 * c2;
                float2 x = *(const float2*)(base + e);
                hp[kc_in * 2 + kh] = cvt_f16x2(x.y, x.x);
            }
        }
        uint32_t off = bn * 1024 + chunk * 512 + lane * 16;
        *(uint4*)(&g_kf[bh][kt][off]) = make_uint4(hp[0], hp[1], hp[2], hp[3]);
    } else {
        const int e = bn * 8 + trow;
        #pragma unroll
        for (int kc_in = 0; kc_in < 2; kc_in++) {
            #pragma unroll
            for (int kh = 0; kh < 2; kh++) {
                int jb = kt * 64 + (chunk * 2 + kc_in) * 16 + kh * 8 + 2 * c2;
                float x0 = v[((size_t)(b * NS + jb) * NH + h) * NE + e];
                float x1 = v[((size_t)(b * NS + jb + 1) * NH + h) * NE + e];
                hp[kc_in * 2 + kh] = cvt_f16x2(x1, x0);
            }
        }
        uint32_t off = bn * 1024 + chunk * 512 + lane * 16;
        *(uint4*)(&g_vf[bh][kt][off]) = make_uint4(hp[0], hp[1], hp[2], hp[3]);
    }
}

// ---------------- attention: 2-pass fp16 flash (Q/P split, K/V single) ----------------
// smem: buf0 [0,16K) = K|V, buf1 [16K,32K), masks at 32K
#define SM_BYTES (32768 + 256)

__global__ __launch_bounds__(256, 1) void attn_mma_kernel(const float* __restrict__ q,
                                                          float* __restrict__ outV,
                                                          float* __restrict__ outA,
                                                          float* __restrict__ outE) {
    extern __shared__ __align__(16) char sm[];
    const int tid = threadIdx.x;
    const int w = tid >> 5;
    const int lane = tid & 31;
    const int c2 = lane & 3, trow = lane >> 2;

    const int qt = (NQT - 1) - (blockIdx.x >> 4);
    const int bh = blockIdx.x & 15;
    const int b = bh >> 3, h = bh & 7;
    const int i0 = qt * TQ;
    const int nk = 2 * qt + 2;

    const int i_r0 = i0 + w * 16 + trow;
    const int i_r1 = i_r0 + 8;
    const int i_wmax = i0 + w * 16 + 15;

    const uint32_t smb = smem_u32(sm);

    // Q fragments (hi/lo fp16), SCALE pre-folded (exact: power-of-2)
    uint32_t qh[4][4], ql[4][4];
    {
        const float* q0 = q + ((size_t)(b * NL + i_r0) * NH + h) * NE;
        const float* q1 = q + ((size_t)(b * NL + i_r1) * NH + h) * NE;
        #pragma unroll
        for (int kc = 0; kc < 4; kc++) {
            int e = kc * 16 + 2 * c2;
            float2 a0 = *(const float2*)(q0 + e);
            float2 a1 = *(const float2*)(q1 + e);
            float2 b0 = *(const float2*)(q0 + e + 8);
            float2 b1 = *(const float2*)(q1 + e + 8);
            a0.x *= SCALE; a0.y *= SCALE; a1.x *= SCALE; a1.y *= SCALE;
            b0.x *= SCALE; b0.y *= SCALE; b1.x *= SCALE; b1.y *= SCALE;
            uint32_t p0 = cvt_f16x2(a0.y, a0.x);
            uint32_t p1 = cvt_f16x2(a1.y, a1.x);
            uint32_t p2 = cvt_f16x2(b0.y, b0.x);
            uint32_t p3 = cvt_f16x2(b1.y, b1.x);
            qh[kc][0] = p0; qh[kc][1] = p1; qh[kc][2] = p2; qh[kc][3] = p3;
            float2 f0 = unpack_f16x2(p0), f1 = unpack_f16x2(p1);
            float2 f2 = unpack_f16x2(p2), f3 = unpack_f16x2(p3);
            ql[kc][0] = cvt_f16x2(a0.y - f0.y, a0.x - f0.x);
            ql[kc][1] = cvt_f16x2(a1.y - f1.y, a1.x - f1.x);
            ql[kc][2] = cvt_f16x2(b0.y - f2.y, b0.x - f2.x);
            ql[kc][3] = cvt_f16x2(b1.y - f3.y, b1.x - f3.x);
        }
    }

    float sacc[8][4];
    float oacc[8][4];
    #pragma unroll
    for (int bn = 0; bn < 8; bn++)
        #pragma unroll
        for (int u = 0; u < 4; u++) { sacc[bn][u] = 0.0f; oacc[bn][u] = 0.0f; }

    float lsum0 = 0.0f, lsum1 = 0.0f, esum0 = 0.0f, esum1 = 0.0f;
    float* Arow0 = outA + ((size_t)bh * NL + i_r0) * NS;
    float* Arow1 = outA + ((size_t)bh * NL + i_r1) * NS;

    auto stageKV = [&](int bufid, int kt) {
        const char* srcK = (const char*)g_kf[bh][kt];
        const char* srcV = (const char*)g_vf[bh][kt];
        uint32_t dst = smb + bufid * 16384;
        #pragma unroll
        for (int i = 0; i < 2; i++) {
            uint32_t off = (uint32_t)(i * 256 + tid) * 16;
            cpa16(dst + off, srcK + off);
            cpa16(dst + 8192 + off, srcV + off);
        }
        if (tid < 16)
            *(uint32_t*)(sm + 32768 + bufid * 64 + tid * 4) =
                *(const uint32_t*)(g_mk + b * NS + kt * 64 + tid * 4);
    };
    auto stageK = [&](int bufid, int kt) {
        const char* srcK = (const char*)g_kf[bh][kt];
        uint32_t dst = smb + bufid * 16384;
        #pragma unroll
        for (int i = 0; i < 2; i++) {
            uint32_t off = (uint32_t)(i * 256 + tid) * 16;
            cpa16(dst + off, srcK + off);
        }
        if (tid < 16)
            *(uint32_t*)(sm + 32768 + bufid * 64 + tid * 4) =
                *(const uint32_t*)(g_mk + b * NS + kt * 64 + tid * 4);
    };

    // ================= PASS 1: lsum/esum + AV (no A store) =================
    stageKV(0, 0);
    CPA_COMMIT();

    int buf = 0;
    for (int kt = 0; kt < nk; kt++) {
        if (kt + 1 < nk) { stageKV(buf ^ 1, kt + 1); CPA_COMMIT(); CPA_WAIT1(); }
        else CPA_WAIT0();
        __syncthreads();

        const int j0 = kt * TN;
        if (j0 <= i_wmax) {
            const char* bufp = sm + buf * 16384;
            const unsigned char* msk = (const unsigned char*)(sm + 32768 + buf * 64);

            // ---- QK: 2-pass (Qhi + Qlo) x single-fp16 K ----
            #pragma unroll
            for (int bn = 0; bn < 8; bn++) {
                uint4 h0 = *(const uint4*)(bufp + bn * 1024 + lane * 16);
                uint4 h1 = *(const uint4*)(bufp + bn * 1024 + 512 + lane * 16);
                mma16816(sacc[bn], qh[0], h0.x, h0.y);
                mma16816(sacc[bn], qh[1], h0.z, h0.w);
                mma16816(sacc[bn], qh[2], h1.x, h1.y);
                mma16816(sacc[bn], qh[3], h1.z, h1.w);
                mma16816(sacc[bn], ql[0], h0.x, h0.y);
                mma16816(sacc[bn], ql[1], h0.z, h0.w);
                mma16816(sacc[bn], ql[2], h1.x, h1.y);
                mma16816(sacc[bn], ql[3], h1.z, h1.w);
            }

            // ---- epilogue: exp, sums, P hi/lo frags ----
            uint32_t pa_hi[4][4], pa_lo[4][4];
            #pragma unroll
            for (int bn = 0; bn < 8; bn++) {
                int colb = j0 + bn * 8 + 2 * c2;
                float s00 = sacc[bn][0], s01 = sacc[bn][1];
                float s10 = sacc[bn][2], s11 = sacc[bn][3];
                unsigned char m0 = msk[bn * 8 + 2 * c2];
                unsigned char m1 = msk[bn * 8 + 2 * c2 + 1];
                float e00 = (m0 || colb > i_r0) ? 0.0f : __expf(s00);
                float e01 = (m1 || colb + 1 > i_r0) ? 0.0f : __expf(s01);
                float e10 = (m0 || colb > i_r1) ? 0.0f : __expf(s10);
                float e11 = (m1 || colb + 1 > i_r1) ? 0.0f : __expf(s11);
                lsum0 += e00 + e01; esum0 += e00 * s00 + e01 * s01;
                lsum1 += e10 + e11; esum1 += e10 * s10 + e11 * s11;
                int kc = bn >> 1, s0i = (bn & 1) * 2;
                uint32_t h0 = cvt_f16x2(e01, e00);
                uint32_t h1 = cvt_f16x2(e11, e10);
                pa_hi[kc][s0i + 0] = h0;
                pa_hi[kc][s0i + 1] = h1;
                float2 f0 = unpack_f16x2(h0), f1 = unpack_f16x2(h1);
                pa_lo[kc][s0i + 0] = cvt_f16x2(e01 - f0.y, e00 - f0.x);
                pa_lo[kc][s0i + 1] = cvt_f16x2(e11 - f1.y, e10 - f1.x);
                sacc[bn][0] = 0.0f; sacc[bn][1] = 0.0f;
                sacc[bn][2] = 0.0f; sacc[bn][3] = 0.0f;
            }

            // ---- AV: 2-pass (Phi + Plo) x single-fp16 V ----
            #pragma unroll
            for (int bn = 0; bn < 8; bn++) {
                uint4 h0 = *(const uint4*)(bufp + 8192 + bn * 1024 + lane * 16);
                uint4 h1 = *(const uint4*)(bufp + 8192 + bn * 1024 + 512 + lane * 16);
                mma16816(oacc[bn], pa_hi[0], h0.x, h0.y);
                mma16816(oacc[bn], pa_hi[1], h0.z, h0.w);
                mma16816(oacc[bn], pa_hi[2], h1.x, h1.y);
                mma16816(oacc[bn], pa_hi[3], h1.z, h1.w);
                mma16816(oacc[bn], pa_lo[0], h0.x, h0.y);
                mma16816(oacc[bn], pa_lo[1], h0.z, h0.w);
                mma16816(oacc[bn], pa_lo[2], h1.x, h1.y);
                mma16816(oacc[bn], pa_lo[3], h1.z, h1.w);
            }
        }
        buf ^= 1;
        __syncthreads();
    }

    // ---- stats: quad reduce, V write, entropy ----
    lsum0 += __shfl_xor_sync(0xffffffffu, lsum0, 1);
    lsum0 += __shfl_xor_sync(0xffffffffu, lsum0, 2);
    lsum1 += __shfl_xor_sync(0xffffffffu, lsum1, 1);
    lsum1 += __shfl_xor_sync(0xffffffffu, lsum1, 2);
    esum0 += __shfl_xor_sync(0xffffffffu, esum0, 1);
    esum0 += __shfl_xor_sync(0xffffffffu, esum0, 2);
    esum1 += __shfl_xor_sync(0xffffffffu, esum1, 1);
    esum1 += __shfl_xor_sync(0xffffffffu, esum1, 2);

    const bool mq0 = g_mq[b * NL + i_r0] != 0;
    const bool mq1 = g_mq[b * NL + i_r1] != 0;
    const float inv0 = mq0 ? 0.0f : 1.0f / lsum0;
    const float inv1 = mq1 ? 0.0f : 1.0f / lsum1;

    float* vo0 = outV + ((size_t)(b * NL + i_r0) * NH + h) * NE;
    float* vo1 = outV + ((size_t)(b * NL + i_r1) * NH + h) * NE;
    #pragma unroll
    for (int bn = 0; bn < 8; bn++) {
        int e0 = bn * 8 + 2 * c2;
        *(float2*)(vo0 + e0) = make_float2(oacc[bn][0] * inv0, oacc[bn][1] * inv0);
        *(float2*)(vo1 + e0) = make_float2(oacc[bn][2] * inv1, oacc[bn][3] * inv1);
    }
    if (c2 == 0) {
        outE[bh * NL + i_r0] = mq0 ? 0.0f : (__logf(lsum0) - esum0 / lsum0);
        outE[bh * NL + i_r1] = mq1 ? 0.0f : (__logf(lsum1) - esum1 / lsum1);
    }

    const float4 z4 = make_float4(0, 0, 0, 0);

    // ---- column tail zero-fill (j >= nk*64) ----
    {
        const int nk16 = nk * 16;
        #pragma unroll 1
        for (int rr = 0; rr < 16; rr++) {
            const int row = i0 + w * 16 + rr;
            float4* Ar = (float4*)(outA + ((size_t)bh * NL + row) * NS);
            for (int c4 = nk16 + lane; c4 < NS / 4; c4 += 32)
                Ar[c4] = z4;
        }
    }

    // ================= PASS 2: recompute scores, write normalized A =================
    __syncthreads();
    stageK(0, 0);
    CPA_COMMIT();

    buf = 0;
    for (int kt = 0; kt < nk; kt++) {
        if (kt + 1 < nk) { stageK(buf ^ 1, kt + 1); CPA_COMMIT(); CPA_WAIT1(); }
        else CPA_WAIT0();
        __syncthreads();

        const int j0 = kt * TN;
        if (j0 <= i_wmax) {
            const char* bufp = sm + buf * 16384;
            const unsigned char* msk = (const unsigned char*)(sm + 32768 + buf * 64);

            #pragma unroll
            for (int bn = 0; bn < 8; bn++) {
                uint4 h0 = *(const uint4*)(bufp + bn * 1024 + lane * 16);
                uint4 h1 = *(const uint4*)(bufp + bn * 1024 + 512 + lane * 16);
                mma16816(sacc[bn], qh[0], h0.x, h0.y);
                mma16816(sacc[bn], qh[1], h0.z, h0.w);
                mma16816(sacc[bn], qh[2], h1.x, h1.y);
                mma16816(sacc[bn], qh[3], h1.z, h1.w);
                mma16816(sacc[bn], ql[0], h0.x, h0.y);
                mma16816(sacc[bn], ql[1], h0.z, h0.w);
                mma16816(sacc[bn], ql[2], h1.x, h1.y);
                mma16816(sacc[bn], ql[3], h1.z, h1.w);
            }

            #pragma unroll
            for (int bn = 0; bn < 8; bn++) {
                int colb = j0 + bn * 8 + 2 * c2;
                float s00 = sacc[bn][0], s01 = sacc[bn][1];
                float s10 = sacc[bn][2], s11 = sacc[bn][3];
                unsigned char m0 = msk[bn * 8 + 2 * c2];
                unsigned char m1 = msk[bn * 8 + 2 * c2 + 1];
                float a00 = (m0 || colb > i_r0) ? 0.0f : __expf(s00) * inv0;
                float a01 = (m1 || colb + 1 > i_r0) ? 0.0f : __expf(s01) * inv0;
                float a10 = (m0 || colb > i_r1) ? 0.0f : __expf(s10) * inv1;
                float a11 = (m1 || colb + 1 > i_r1) ? 0.0f : __expf(s11) * inv1;
                *(float2*)(Arow0 + colb) = make_float2(a00, a01);
                *(float2*)(Arow1 + colb) = make_float2(a10, a11);
                sacc[bn][0] = 0.0f; sacc[bn][1] = 0.0f;
                sacc[bn][2] = 0.0f; sacc[bn][3] = 0.0f;
            }
        } else {
            // above-diagonal warp tile: zeros
            #pragma unroll
            for (int rr = 0; rr < 2; rr++) {
                float* Ar = (rr == 0 ? Arow0 : Arow1) + j0;
                #pragma unroll
                for (int u = 0; u < 4; u++)
                    ((float4*)Ar)[c2 * 4 + u] = z4;
            }
        }
        buf ^= 1;
        __syncthreads();
    }
}

extern "C" void kernel_launch(void* const* d_in, const int* in_sizes, int n_in,
                              void* d_out, int out_size) {
    const float* q = (const float*)d_in[0];
    const float* k = (const float*)d_in[1];
    const float* v = (const float*)d_in[2];
    const void* mk = d_in[3];
    const void* mq = d_in[4];

    float* outV = (float*)d_out;
    float* outA = outV + (size_t)NB * NL * NH * NE;
    float* outE = outA + (size_t)NB * NH * NL * NS;

    cudaFuncSetAttribute(attn_mma_kernel,
                         cudaFuncAttributeMaxDynamicSharedMemorySize, SM_BYTES);

    prep_kernel<<<2064, 256>>>(k, v, mk, mq);
    attn_mma_kernel<<<NBH * NQT, 256, SM_BYTES>>>(q, outV, outA, outE);
}

// round 11
// speedup vs baseline: 1.5730x; 1.1039x over previous
#include <cuda_runtime.h>
#include <cuda_fp16.h>
#include <math.h>
#include <stdint.h>

#define NB 2
#define NL 2048
#define NS 2048
#define NH 8
#define NE 64
#define NBH 16
#define SCALE 0.125f
#define TQ 128
#define TN 64
#define NQT (NL / TQ)
#define NKT (NS / TN)

// ---------------- device scratch (single fp16 tiles) ----------------
__device__ __align__(16) uint8_t g_kf[NBH][NKT][8192];
__device__ __align__(16) uint8_t g_vf[NBH][NKT][8192];
__device__ unsigned char g_mk[NB * NS];
__device__ unsigned char g_mq[NB * NL];

// ---------------- helpers ----------------
__device__ __forceinline__ uint32_t cvt_f16x2(float hi, float lo) {
    uint32_t r;
    asm("cvt.rn.f16x2.f32 %0, %1, %2;" : "=r"(r) : "f"(hi), "f"(lo));
    return r;
}
__device__ __forceinline__ float2 unpack_f16x2(uint32_t p) {
    __half2 h = *reinterpret_cast<__half2*>(&p);
    return __half22float2(h);
}
__device__ __forceinline__ uint32_t smem_u32(const void* p) {
    uint32_t a;
    asm("{ .reg .u64 t; cvta.to.shared.u64 t, %1; cvt.u32.u64 %0, t; }" : "=r"(a) : "l"(p));
    return a;
}
__device__ __forceinline__ void mma16816(float d[4], const uint32_t a[4],
                                         uint32_t b0, uint32_t b1) {
    asm volatile(
        "mma.sync.aligned.m16n8k16.row.col.f32.f16.f16.f32 "
        "{%0,%1,%2,%3},{%4,%5,%6,%7},{%8,%9},{%0,%1,%2,%3};"
        : "+f"(d[0]), "+f"(d[1]), "+f"(d[2]), "+f"(d[3])
        : "r"(a[0]), "r"(a[1]), "r"(a[2]), "r"(a[3]), "r"(b0), "r"(b1));
}
__device__ __forceinline__ void cpa16(uint32_t dst, const void* src) {
    asm volatile("cp.async.cg.shared.global [%0], [%1], 16;" :: "r"(dst), "l"(src));
}
#define CPA_COMMIT() asm volatile("cp.async.commit_group;" ::: "memory")
#define CPA_WAIT0()  asm volatile("cp.async.wait_group 0;" ::: "memory")
#define CPA_WAIT1()  asm volatile("cp.async.wait_group 1;" ::: "memory")

// ---------------- prep: fp16 fragment tiles + mask normalization ----------------
__global__ __launch_bounds__(256) void prep_kernel(const float* __restrict__ k,
                                                   const float* __restrict__ v,
                                                   const void* mk_raw,
                                                   const void* mq_raw) {
    if (blockIdx.x >= 2048) {
        __shared__ int sh_f32, sh_u8;
        if (threadIdx.x == 0) { sh_f32 = 0; sh_u8 = 0; }
        __syncthreads();
        const uint32_t* p32 = (const uint32_t*)mk_raw;
        int f32 = 0, u8 = 0;
        #pragma unroll
        for (int it = 0; it < 4; it++) {
            uint32_t wv = p32[it * 256 + threadIdx.x];
            if (((wv >> 24) & 0xff) == 0x3f) f32 = 1;
            if (wv & 0x00ffff00u) u8 = 1;
        }
        if (f32) atomicOr(&sh_f32, 1);
        if (u8) atomicOr(&sh_u8, 1);
        __syncthreads();
        int mode = sh_f32 ? 2 : (sh_u8 ? 1 : 0);
        int idx = (blockIdx.x - 2048) * 256 + threadIdx.x;
        unsigned char vk, vq;
        if (mode == 2) { vk = ((const float*)mk_raw)[idx] != 0.0f; vq = ((const float*)mq_raw)[idx] != 0.0f; }
        else if (mode == 1) { vk = ((const unsigned char*)mk_raw)[idx] != 0; vq = ((const unsigned char*)mq_raw)[idx] != 0; }
        else { vk = ((const int*)mk_raw)[idx] != 0; vq = ((const int*)mq_raw)[idx] != 0; }
        g_mk[idx] = vk;
        g_mq[idx] = vq;
        return;
    }

    const int kind = blockIdx.x >> 10;                   // 0 = K, 1 = V^T
    const int c = ((blockIdx.x & 1023) << 8) + threadIdx.x;
    const int lane = c & 31;
    const int chunk = (c >> 5) & 1;
    const int bn = (c >> 6) & 7;
    const int kt = (c >> 9) & 31;
    const int bh = c >> 14;
    const int b = bh >> 3, h = bh & 7;
    const int c2 = lane & 3, trow = lane >> 2;

    uint32_t hp[4];
    if (kind == 0) {
        const int j = kt * 64 + bn * 8 + trow;
        const float* base = k + ((size_t)(b * NS + j) * NH + h) * NE;
        #pragma unroll
        for (int kc_in = 0; kc_in < 2; kc_in++) {
            #pragma unroll
            for (int kh = 0; kh < 2; kh++) {
                int e = (chunk * 2 + kc_in) * 16 + kh * 8 + 2 * c2;
                float2 x = *(const float2*)(base + e);
                hp[kc_in * 2 + kh] = cvt_f16x2(x.y, x.x);
            }
        }
        uint32_t off = bn * 1024 + chunk * 512 + lane * 16;
        *(uint4*)(&g_kf[bh][kt][off]) = make_uint4(hp[0], hp[1], hp[2], hp[3]);
    } else {
        const int e = bn * 8 + trow;
        #pragma unroll
        for (int kc_in = 0; kc_in < 2; kc_in++) {
            #pragma unroll
            for (int kh = 0; kh < 2; kh++) {
                int jb = kt * 64 + (chunk * 2 + kc_in) * 16 + kh * 8 + 2 * c2;
                float x0 = v[((size_t)(b * NS + jb) * NH + h) * NE + e];
                float x1 = v[((size_t)(b * NS + jb + 1) * NH + h) * NE + e];
                hp[kc_in * 2 + kh] = cvt_f16x2(x1, x0);
            }
        }
        uint32_t off = bn * 1024 + chunk * 512 + lane * 16;
        *(uint4*)(&g_vf[bh][kt][off]) = make_uint4(hp[0], hp[1], hp[2], hp[3]);
    }
}

// ---------------- attention: 2-pass fp16 flash ----------------
// pass 1: single-fp16 QK + single-fp16 AV (stats + V)
// pass 2: Q hi/lo split QK (full precision for A), inv folded into exp
#define SM_BYTES (32768 + 256)

__global__ __launch_bounds__(256, 1) void attn_mma_kernel(const float* __restrict__ q,
                                                          float* __restrict__ outV,
                                                          float* __restrict__ outA,
                                                          float* __restrict__ outE) {
    extern __shared__ __align__(16) char sm[];
    const int tid = threadIdx.x;
    const int w = tid >> 5;
    const int lane = tid & 31;
    const int c2 = lane & 3, trow = lane >> 2;

    const int qt = (NQT - 1) - (blockIdx.x >> 4);
    const int bh = blockIdx.x & 15;
    const int b = bh >> 3, h = bh & 7;
    const int i0 = qt * TQ;
    const int nk = 2 * qt + 2;

    const int i_r0 = i0 + w * 16 + trow;
    const int i_r1 = i_r0 + 8;
    const int i_wmax = i0 + w * 16 + 15;

    const uint32_t smb = smem_u32(sm);

    // Q fragments (hi/lo fp16), SCALE pre-folded (exact: power-of-2)
    uint32_t qh[4][4], ql[4][4];
    {
        const float* q0 = q + ((size_t)(b * NL + i_r0) * NH + h) * NE;
        const float* q1 = q + ((size_t)(b * NL + i_r1) * NH + h) * NE;
        #pragma unroll
        for (int kc = 0; kc < 4; kc++) {
            int e = kc * 16 + 2 * c2;
            float2 a0 = *(const float2*)(q0 + e);
            float2 a1 = *(const float2*)(q1 + e);
            float2 b0 = *(const float2*)(q0 + e + 8);
            float2 b1 = *(const float2*)(q1 + e + 8);
            a0.x *= SCALE; a0.y *= SCALE; a1.x *= SCALE; a1.y *= SCALE;
            b0.x *= SCALE; b0.y *= SCALE; b1.x *= SCALE; b1.y *= SCALE;
            uint32_t p0 = cvt_f16x2(a0.y, a0.x);
            uint32_t p1 = cvt_f16x2(a1.y, a1.x);
            uint32_t p2 = cvt_f16x2(b0.y, b0.x);
            uint32_t p3 = cvt_f16x2(b1.y, b1.x);
            qh[kc][0] = p0; qh[kc][1] = p1; qh[kc][2] = p2; qh[kc][3] = p3;
            float2 f0 = unpack_f16x2(p0), f1 = unpack_f16x2(p1);
            float2 f2 = unpack_f16x2(p2), f3 = unpack_f16x2(p3);
            ql[kc][0] = cvt_f16x2(a0.y - f0.y, a0.x - f0.x);
            ql[kc][1] = cvt_f16x2(a1.y - f1.y, a1.x - f1.x);
            ql[kc][2] = cvt_f16x2(b0.y - f2.y, b0.x - f2.x);
            ql[kc][3] = cvt_f16x2(b1.y - f3.y, b1.x - f3.x);
        }
    }

    float sacc[8][4];
    float oacc[8][4];
    #pragma unroll
    for (int bn = 0; bn < 8; bn++)
        #pragma unroll
        for (int u = 0; u < 4; u++) { sacc[bn][u] = 0.0f; oacc[bn][u] = 0.0f; }

    float lsum0 = 0.0f, lsum1 = 0.0f, esum0 = 0.0f, esum1 = 0.0f;
    float* Arow0 = outA + ((size_t)bh * NL + i_r0) * NS;
    float* Arow1 = outA + ((size_t)bh * NL + i_r1) * NS;

    auto stageKV = [&](int bufid, int kt) {
        const char* srcK = (const char*)g_kf[bh][kt];
        const char* srcV = (const char*)g_vf[bh][kt];
        uint32_t dst = smb + bufid * 16384;
        #pragma unroll
        for (int i = 0; i < 2; i++) {
            uint32_t off = (uint32_t)(i * 256 + tid) * 16;
            cpa16(dst + off, srcK + off);
            cpa16(dst + 8192 + off, srcV + off);
        }
        if (tid < 16)
            *(uint32_t*)(sm + 32768 + bufid * 64 + tid * 4) =
                *(const uint32_t*)(g_mk + b * NS + kt * 64 + tid * 4);
    };
    auto stageK = [&](int bufid, int kt) {
        const char* srcK = (const char*)g_kf[bh][kt];
        uint32_t dst = smb + bufid * 16384;
        #pragma unroll
        for (int i = 0; i < 2; i++) {
            uint32_t off = (uint32_t)(i * 256 + tid) * 16;
            cpa16(dst + off, srcK + off);
        }
        if (tid < 16)
            *(uint32_t*)(sm + 32768 + bufid * 64 + tid * 4) =
                *(const uint32_t*)(g_mk + b * NS + kt * 64 + tid * 4);
    };

    // ================= PASS 1: lsum/esum + AV (single-fp16 Q and P) =================
    stageKV(0, 0);
    CPA_COMMIT();

    int buf = 0;
    for (int kt = 0; kt < nk; kt++) {
        if (kt + 1 < nk) { stageKV(buf ^ 1, kt + 1); CPA_COMMIT(); CPA_WAIT1(); }
        else CPA_WAIT0();
        __syncthreads();

        const int j0 = kt * TN;
        if (j0 <= i_wmax) {
            const char* bufp = sm + buf * 16384;
            const unsigned char* msk = (const unsigned char*)(sm + 32768 + buf * 64);

            // ---- QK: single-pass (Qhi only) ----
            #pragma unroll
            for (int bn = 0; bn < 8; bn++) {
                uint4 h0 = *(const uint4*)(bufp + bn * 1024 + lane * 16);
                uint4 h1 = *(const uint4*)(bufp + bn * 1024 + 512 + lane * 16);
                mma16816(sacc[bn], qh[0], h0.x, h0.y);
                mma16816(sacc[bn], qh[1], h0.z, h0.w);
                mma16816(sacc[bn], qh[2], h1.x, h1.y);
                mma16816(sacc[bn], qh[3], h1.z, h1.w);
            }

            // ---- epilogue: exp, sums, P frags (single fp16) ----
            uint32_t pa_hi[4][4];
            #pragma unroll
            for (int bn = 0; bn < 8; bn++) {
                int colb = j0 + bn * 8 + 2 * c2;
                float s00 = sacc[bn][0], s01 = sacc[bn][1];
                float s10 = sacc[bn][2], s11 = sacc[bn][3];
                unsigned char m0 = msk[bn * 8 + 2 * c2];
                unsigned char m1 = msk[bn * 8 + 2 * c2 + 1];
                float e00 = (m0 || colb > i_r0) ? 0.0f : __expf(s00);
                float e01 = (m1 || colb + 1 > i_r0) ? 0.0f : __expf(s01);
                float e10 = (m0 || colb > i_r1) ? 0.0f : __expf(s10);
                float e11 = (m1 || colb + 1 > i_r1) ? 0.0f : __expf(s11);
                lsum0 += e00 + e01; esum0 += e00 * s00 + e01 * s01;
                lsum1 += e10 + e11; esum1 += e10 * s10 + e11 * s11;
                int kc = bn >> 1, s0i = (bn & 1) * 2;
                pa_hi[kc][s0i + 0] = cvt_f16x2(e01, e00);
                pa_hi[kc][s0i + 1] = cvt_f16x2(e11, e10);
                sacc[bn][0] = 0.0f; sacc[bn][1] = 0.0f;
                sacc[bn][2] = 0.0f; sacc[bn][3] = 0.0f;
            }

            // ---- AV: single-pass (Phi only) ----
            #pragma unroll
            for (int bn = 0; bn < 8; bn++) {
                uint4 h0 = *(const uint4*)(bufp + 8192 + bn * 1024 + lane * 16);
                uint4 h1 = *(const uint4*)(bufp + 8192 + bn * 1024 + 512 + lane * 16);
                mma16816(oacc[bn], pa_hi[0], h0.x, h0.y);
                mma16816(oacc[bn], pa_hi[1], h0.z, h0.w);
                mma16816(oacc[bn], pa_hi[2], h1.x, h1.y);
                mma16816(oacc[bn], pa_hi[3], h1.z, h1.w);
            }
        }
        buf ^= 1;
        __syncthreads();
    }

    // ---- stats: quad reduce, V write, entropy ----
    lsum0 += __shfl_xor_sync(0xffffffffu, lsum0, 1);
    lsum0 += __shfl_xor_sync(0xffffffffu, lsum0, 2);
    lsum1 += __shfl_xor_sync(0xffffffffu, lsum1, 1);
    lsum1 += __shfl_xor_sync(0xffffffffu, lsum1, 2);
    esum0 += __shfl_xor_sync(0xffffffffu, esum0, 1);
    esum0 += __shfl_xor_sync(0xffffffffu, esum0, 2);
    esum1 += __shfl_xor_sync(0xffffffffu, esum1, 1);
    esum1 += __shfl_xor_sync(0xffffffffu, esum1, 2);

    const bool mq0 = g_mq[b * NL + i_r0] != 0;
    const bool mq1 = g_mq[b * NL + i_r1] != 0;
    const float inv0 = mq0 ? 0.0f : 1.0f / lsum0;
    const float inv1 = mq1 ? 0.0f : 1.0f / lsum1;
    const float ls0 = __logf(inv0);     // -inf if masked -> exp() = 0
    const float ls1 = __logf(inv1);

    float* vo0 = outV + ((size_t)(b * NL + i_r0) * NH + h) * NE;
    float* vo1 = outV + ((size_t)(b * NL + i_r1) * NH + h) * NE;
    #pragma unroll
    for (int bn = 0; bn < 8; bn++) {
        int e0 = bn * 8 + 2 * c2;
        *(float2*)(vo0 + e0) = make_float2(oacc[bn][0] * inv0, oacc[bn][1] * inv0);
        *(float2*)(vo1 + e0) = make_float2(oacc[bn][2] * inv1, oacc[bn][3] * inv1);
    }
    if (c2 == 0) {
        outE[bh * NL + i_r0] = mq0 ? 0.0f : (__logf(lsum0) - esum0 / lsum0);
        outE[bh * NL + i_r1] = mq1 ? 0.0f : (__logf(lsum1) - esum1 / lsum1);
    }

    const float4 z4 = make_float4(0, 0, 0, 0);

    // ---- column tail zero-fill (j >= nk*64) ----
    {
        const int nk16 = nk * 16;
        #pragma unroll 1
        for (int rr = 0; rr < 16; rr++) {
            const int row = i0 + w * 16 + rr;
            float4* Ar = (float4*)(outA + ((size_t)bh * NL + row) * NS);
            for (int c4 = nk16 + lane; c4 < NS / 4; c4 += 32)
                Ar[c4] = z4;
        }
    }

    // ================= PASS 2: full-precision QK, write normalized A =================
    __syncthreads();
    stageK(0, 0);
    CPA_COMMIT();

    buf = 0;
    for (int kt = 0; kt < nk; kt++) {
        if (kt + 1 < nk) { stageK(buf ^ 1, kt + 1); CPA_COMMIT(); CPA_WAIT1(); }
        else CPA_WAIT0();
        __syncthreads();

        const int j0 = kt * TN;
        if (j0 <= i_wmax) {
            const char* bufp = sm + buf * 16384;
            const unsigned char* msk = (const unsigned char*)(sm + 32768 + buf * 64);

            #pragma unroll
            for (int bn = 0; bn < 8; bn++) {
                uint4 h0 = *(const uint4*)(bufp + bn * 1024 + lane * 16);
                uint4 h1 = *(const uint4*)(bufp + bn * 1024 + 512 + lane * 16);
                mma16816(sacc[bn], qh[0], h0.x, h0.y);
                mma16816(sacc[bn], qh[1], h0.z, h0.w);
                mma16816(sacc[bn], qh[2], h1.x, h1.y);
                mma16816(sacc[bn], qh[3], h1.z, h1.w);
                mma16816(sacc[bn], ql[0], h0.x, h0.y);
                mma16816(sacc[bn], ql[1], h0.z, h0.w);
                mma16816(sacc[bn], ql[2], h1.x, h1.y);
                mma16816(sacc[bn], ql[3], h1.z, h1.w);
            }

            #pragma unroll
            for (int bn = 0; bn < 8; bn++) {
                int colb = j0 + bn * 8 + 2 * c2;
                float s00 = sacc[bn][0], s01 = sacc[bn][1];
                float s10 = sacc[bn][2], s11 = sacc[bn][3];
                unsigned char m0 = msk[bn * 8 + 2 * c2];
                unsigned char m1 = msk[bn * 8 + 2 * c2 + 1];
                float a00 = (m0 || colb > i_r0) ? 0.0f : __expf(s00 + ls0);
                float a01 = (m1 || colb + 1 > i_r0) ? 0.0f : __expf(s01 + ls0);
                float a10 = (m0 || colb > i_r1) ? 0.0f : __expf(s10 + ls1);
                float a11 = (m1 || colb + 1 > i_r1) ? 0.0f : __expf(s11 + ls1);
                *(float2*)(Arow0 + colb) = make_float2(a00, a01);
                *(float2*)(Arow1 + colb) = make_float2(a10, a11);
                sacc[bn][0] = 0.0f; sacc[bn][1] = 0.0f;
                sacc[bn][2] = 0.0f; sacc[bn][3] = 0.0f;
            }
        } else {
            // above-diagonal warp tile: zeros
            #pragma unroll
            for (int rr = 0; rr < 2; rr++) {
                float* Ar = (rr == 0 ? Arow0 : Arow1) + j0;
                #pragma unroll
                for (int u = 0; u < 4; u++)
                    ((float4*)Ar)[c2 * 4 + u] = z4;
            }
        }
        buf ^= 1;
        __syncthreads();
    }
}

extern "C" void kernel_launch(void* const* d_in, const int* in_sizes, int n_in,
                              void* d_out, int out_size) {
    const float* q = (const float*)d_in[0];
    const float* k = (const float*)d_in[1];
    const float* v = (const float*)d_in[2];
    const void* mk = d_in[3];
    const void* mq = d_in[4];

    float* outV = (float*)d_out;
    float* outA = outV + (size_t)NB * NL * NH * NE;
    float* outE = outA + (size_t)NB * NH * NL * NS;

    cudaFuncSetAttribute(attn_mma_kernel,
                         cudaFuncAttributeMaxDynamicSharedMemorySize, SM_BYTES);

    prep_kernel<<<2064, 256>>>(k, v, mk, mq);
    attn_mma_kernel<<<NBH * NQT, 256, SM_BYTES>>>(q, outV, outA, outE);
}